// round 13
// baseline (speedup 1.0000x reference)
#include <cuda_runtime.h>
#include <cuda_bf16.h>
#include <math.h>
#include <stdint.h>

// ---------------- problem constants ----------------
#define HIMG 256
#define WIMG 256
#define CDIM 256
#define LTOK (HIMG*WIMG)          // 65536
#define QKVC 768
#define NHEAD 4
#define HD 32
#define WS 16
#define NTOK_W 256
#define SS 32
#define NTOK_S 1024
#define ASZ 8
#define NANC 64
#define AH 64
#define TW_N 961
#define TS_N 1521
#define LOG100 4.60517018598809f

// ---------------- scratch (__device__ globals: no allocs allowed) ----------------
__device__ float g_qkv[(size_t)LTOK * QKVC];
__device__ float g_merged[(size_t)LTOK * CDIM];     // [xw | xs] tf32-rounded
__device__ float g_xr[(size_t)LTOK * CDIM];         // x tf32-rounded
__device__ float g_pooled[4096 * CDIM];
__device__ float g_anchor[4096 * 128];
__device__ float g_ancn[4096 * 128];
__device__ float g_xm[64 * NHEAD * NANC * HD];
__device__ float g_wqkv[CDIM * QKVC];
__device__ float g_wanc[CDIM * 128];
__device__ float g_wproj[CDIM * CDIM];
__device__ float g_btw[TW_N * NHEAD];
__device__ float g_bts1[TS_N * NHEAD];
__device__ float g_bts2[TS_N * NHEAD];
__device__ float g_biasw[NHEAD * NTOK_W * NTOK_W];    // [h][n][m]
__device__ float g_biasa1[NHEAD * NANC * NTOK_S];     // [h][n2=64][m=1024]
__device__ float g_biasw2a[NHEAD * NTOK_S * NANC];    // [h][n=1024][m=64]

// ---------------- helpers ----------------
__device__ __forceinline__ uint32_t f2tf32u(float x) {
    uint32_t u;
    asm("cvt.rna.tf32.f32 %0, %1;" : "=r"(u) : "f"(x));
    return u;
}
__device__ __forceinline__ float f2tf32(float x) { return __uint_as_float(f2tf32u(x)); }

__device__ __forceinline__ void mma_tf32(float& c0, float& c1, float& c2, float& c3,
                                         uint32_t a0, uint32_t a1, uint32_t a2, uint32_t a3,
                                         uint32_t b0, uint32_t b1) {
    asm volatile(
        "mma.sync.aligned.m16n8k8.row.col.f32.tf32.tf32.f32 "
        "{%0,%1,%2,%3}, {%4,%5,%6,%7}, {%8,%9}, {%0,%1,%2,%3};"
        : "+f"(c0), "+f"(c1), "+f"(c2), "+f"(c3)
        : "r"(a0), "r"(a1), "r"(a2), "r"(a3), "r"(b0), "r"(b1));
}

__device__ __forceinline__ void cp16(void* smem_dst, const void* gsrc) {
    uint32_t s = (uint32_t)__cvta_generic_to_shared(smem_dst);
    asm volatile("cp.async.cg.shared.global [%0], [%1], 16;" :: "r"(s), "l"(gsrc));
}
__device__ __forceinline__ void cp_commit() { asm volatile("cp.async.commit_group;"); }
template<int N> __device__ __forceinline__ void cp_wait() {
    asm volatile("cp.async.wait_group %0;" :: "n"(N));
}

// ---------------- rounding kernels ----------------
__global__ void round_tf32_vec(const float* __restrict__ in, float* __restrict__ out, int n4) {
    int i = blockIdx.x * blockDim.x + threadIdx.x;
    if (i >= n4) return;
    float4 v = ((const float4*)in)[i];
    v.x = f2tf32(v.x); v.y = f2tf32(v.y); v.z = f2tf32(v.z); v.w = f2tf32(v.w);
    ((float4*)out)[i] = v;
}

__global__ void round_weights(const float* __restrict__ qkv_w,
                              const float* __restrict__ anchor_w,
                              const float* __restrict__ proj_w) {
    int i = blockIdx.x * blockDim.x + threadIdx.x;
    int n_qkv = CDIM * QKVC / 4, n_anc = CDIM * 128 / 4, n_proj = CDIM * CDIM / 4;
    const float4* src; float4* dst; int idx;
    if (i < n_qkv) { src = (const float4*)qkv_w; dst = (float4*)g_wqkv; idx = i; }
    else if (i < n_qkv + n_anc) { src = (const float4*)anchor_w; dst = (float4*)g_wanc; idx = i - n_qkv; }
    else if (i < n_qkv + n_anc + n_proj) { src = (const float4*)proj_w; dst = (float4*)g_wproj; idx = i - n_qkv - n_anc; }
    else return;
    float4 v = src[idx];
    v.x = f2tf32(v.x); v.y = f2tf32(v.y); v.z = f2tf32(v.z); v.w = f2tf32(v.w);
    dst[idx] = v;
}

// ---------------- tf32 tensor-core GEMM, cp.async 3-stage, col_base offset ----
// B, bias, C are BASE pointers; all column offsetting happens via col_base here.
#define GEMM_SMEM_BYTES (3*(128*36 + 32*136)*4)
__global__ __launch_bounds__(256) void gemm_tf32(const float* __restrict__ A,
                                                 const float* __restrict__ B,
                                                 const float* __restrict__ bias,
                                                 float* __restrict__ C,
                                                 int M, int N, int K, int col_base) {
    extern __shared__ float smem[];
    float (*As)[128][36] = (float(*)[128][36])smem;
    float (*Bs)[32][136] = (float(*)[32][136])(smem + 3 * 128 * 36);

    int tid = threadIdx.x;
    int wid = tid >> 5;
    int lane = tid & 31;
    int gid = lane >> 2;
    int tig = lane & 3;
    int wm = (wid >> 2) * 64;
    int wn = (wid & 3) * 32;

    int row0 = blockIdx.y * 128;
    int col0 = col_base + blockIdx.x * 128;

    float acc[4][4][4];
    #pragma unroll
    for (int mt = 0; mt < 4; mt++)
        #pragma unroll
        for (int nt = 0; nt < 4; nt++)
            #pragma unroll
            for (int r = 0; r < 4; r++) acc[mt][nt][r] = 0.f;

    auto load_tile = [&](int st, int k0) {
        #pragma unroll
        for (int i = 0; i < 4; i++) {
            int f = tid + i * 256;
            int r = f >> 3, c4 = (f & 7) << 2;
            cp16(&As[st][r][c4], &A[(size_t)(row0 + r) * K + k0 + c4]);
        }
        #pragma unroll
        for (int i = 0; i < 4; i++) {
            int f = tid + i * 256;
            int r = f >> 5, c4 = (f & 31) << 2;
            cp16(&Bs[st][r][c4], &B[(size_t)(k0 + r) * N + col0 + c4]);
        }
        cp_commit();
    };

    int nk = K >> 5;
    load_tile(0, 0);
    if (nk > 1) load_tile(1, 32);
    for (int it = 0; it < nk; it++) {
        int st = it % 3;
        if (it + 2 < nk) { load_tile((it + 2) % 3, (it + 2) << 5); cp_wait<2>(); }
        else if (it + 1 < nk) cp_wait<1>();
        else cp_wait<0>();
        __syncthreads();

        #pragma unroll
        for (int kk = 0; kk < 32; kk += 8) {
            uint32_t af[4][4];
            #pragma unroll
            for (int mt = 0; mt < 4; mt++) {
                int rbase = wm + mt * 16;
                af[mt][0] = __float_as_uint(As[st][rbase + gid    ][kk + tig    ]);
                af[mt][1] = __float_as_uint(As[st][rbase + gid + 8][kk + tig    ]);
                af[mt][2] = __float_as_uint(As[st][rbase + gid    ][kk + tig + 4]);
                af[mt][3] = __float_as_uint(As[st][rbase + gid + 8][kk + tig + 4]);
            }
            uint32_t bf[4][2];
            #pragma unroll
            for (int nt = 0; nt < 4; nt++) {
                int cbase = wn + nt * 8 + gid;
                bf[nt][0] = __float_as_uint(Bs[st][kk + tig    ][cbase]);
                bf[nt][1] = __float_as_uint(Bs[st][kk + tig + 4][cbase]);
            }
            #pragma unroll
            for (int mt = 0; mt < 4; mt++)
                #pragma unroll
                for (int nt = 0; nt < 4; nt++)
                    mma_tf32(acc[mt][nt][0], acc[mt][nt][1], acc[mt][nt][2], acc[mt][nt][3],
                             af[mt][0], af[mt][1], af[mt][2], af[mt][3],
                             bf[nt][0], bf[nt][1]);
        }
        __syncthreads();
    }

    #pragma unroll
    for (int nt = 0; nt < 4; nt++) {
        int col = col0 + wn + nt * 8 + tig * 2;
        float b0 = bias[col], b1 = bias[col + 1];
        #pragma unroll
        for (int mt = 0; mt < 4; mt++) {
            int row = row0 + wm + mt * 16 + gid;
            float2 o0 = make_float2(acc[mt][nt][0] + b0, acc[mt][nt][1] + b1);
            float2 o1 = make_float2(acc[mt][nt][2] + b0, acc[mt][nt][3] + b1);
            *(float2*)&C[(size_t)row * N + col] = o0;
            *(float2*)&C[(size_t)(row + 8) * N + col] = o1;
        }
    }
}

// ---------------- CPB MLPs batched ----------------
__global__ void cpb_mlp3(const float* __restrict__ tw, const float* __restrict__ ts,
                         const float* __restrict__ w1a, const float* __restrict__ b1a,
                         const float* __restrict__ w2a,
                         const float* __restrict__ w1b, const float* __restrict__ b1b,
                         const float* __restrict__ w2b,
                         const float* __restrict__ w1c, const float* __restrict__ b1c,
                         const float* __restrict__ w2c) {
    int set = blockIdx.y;
    const float* table = (set == 0) ? tw : ts;
    int T = (set == 0) ? TW_N : TS_N;
    const float* w1 = (set == 0) ? w1a : (set == 1) ? w1b : w1c;
    const float* b1 = (set == 0) ? b1a : (set == 1) ? b1b : b1c;
    const float* w2 = (set == 0) ? w2a : (set == 1) ? w2b : w2c;
    float* bt = (set == 0) ? g_btw : (set == 1) ? g_bts1 : g_bts2;

    __shared__ float s_w1[1024];
    __shared__ float s_b1[512];
    __shared__ float s_w2[2048];
    for (int i = threadIdx.x; i < 1024; i += blockDim.x) s_w1[i] = w1[i];
    for (int i = threadIdx.x; i < 512;  i += blockDim.x) s_b1[i] = b1[i];
    for (int i = threadIdx.x; i < 2048; i += blockDim.x) s_w2[i] = w2[i];
    __syncthreads();
    int t = blockIdx.x * blockDim.x + threadIdx.x;
    if (t >= T) return;
    float t0 = table[t * 2], t1 = table[t * 2 + 1];
    float a0 = 0.f, a1 = 0.f, a2 = 0.f, a3 = 0.f;
    for (int j = 0; j < 512; j++) {
        float hsum = fmaf(t0, s_w1[j], fmaf(t1, s_w1[512 + j], s_b1[j]));
        float hr = fmaxf(hsum, 0.f);
        a0 = fmaf(hr, s_w2[j * 4 + 0], a0);
        a1 = fmaf(hr, s_w2[j * 4 + 1], a1);
        a2 = fmaf(hr, s_w2[j * 4 + 2], a2);
        a3 = fmaf(hr, s_w2[j * 4 + 3], a3);
    }
    bt[t * 4 + 0] = a0; bt[t * 4 + 1] = a1; bt[t * 4 + 2] = a2; bt[t * 4 + 3] = a3;
}

// ---------------- natural-layout gather [h][n][m] ----------------
__global__ void gather_nat(const float* __restrict__ bt, const int* __restrict__ index,
                           float* __restrict__ out, int Nq, int Nk) {
    int i = blockIdx.x * blockDim.x + threadIdx.x;
    int total = NHEAD * Nq * Nk;
    if (i >= total) return;
    int m = i % Nk;
    int n = (i / Nk) % Nq;
    int h = i / (Nk * Nq);
    int id = index[n * Nk + m];
    float b = bt[id * 4 + h];
    out[i] = 16.f / (1.f + __expf(-b));   // out[h][n][m]
}

// ---------------- avg pool 4x4 (tf32-rounded output) ----------------
__global__ void avgpool4(const float* __restrict__ x, float* __restrict__ pooled) {
    int p = blockIdx.x;
    int ch = threadIdx.x;
    int ph = p >> 6, pw = p & 63;
    float s = 0.f;
    #pragma unroll
    for (int i = 0; i < 4; i++)
        #pragma unroll
        for (int j = 0; j < 4; j++)
            s += x[((size_t)((ph * 4 + i) * WIMG + pw * 4 + j)) * CDIM + ch];
    pooled[(size_t)p * CDIM + ch] = f2tf32(s * 0.0625f);
}

// ---------------- anchor l2 normalize ----------------
__global__ void norm_anchor(const float* __restrict__ a, float* __restrict__ an) {
    int i = blockIdx.x * blockDim.x + threadIdx.x;
    if (i >= 4096 * NHEAD) return;
    int p = i >> 2, h = i & 3;
    const float4* src = (const float4*)(a + (size_t)p * 128 + h * HD);
    float4 v[8];
    float ss = 0.f;
    #pragma unroll
    for (int d = 0; d < 8; d++) {
        v[d] = src[d];
        ss += v[d].x * v[d].x + v[d].y * v[d].y + v[d].z * v[d].z + v[d].w * v[d].w;
    }
    float inv = 1.f / fmaxf(sqrtf(ss), 1e-12f);
    float4* dst = (float4*)(an + (size_t)p * 128 + h * HD);
    #pragma unroll
    for (int d = 0; d < 8; d++) {
        v[d].x *= inv; v[d].y *= inv; v[d].z *= inv; v[d].w *= inv;
        dst[d] = v[d];
    }
}

// =========================================================================
// Tensor-core flash attention (exact R6 versions)
// =========================================================================
#define APAD 36
#define PPAD 68
#define ATT_SMEM_FLOATS (256*APAD + 64*APAD + 64*APAD + 256*PPAD)
#define ATT_SMEM_BYTES (ATT_SMEM_FLOATS*4)

__global__ __launch_bounds__(256) void win_attn_mma(const float* __restrict__ ls) {
    extern __shared__ float sm[];
    float (*sQ)[APAD] = (float(*)[APAD])sm;
    float (*sK)[APAD] = (float(*)[APAD])(sm + 256 * APAD);
    float (*sV)[APAD] = (float(*)[APAD])(sm + 320 * APAD);
    float (*sP)[PPAD] = (float(*)[PPAD])(sm + 384 * APAD);

    int h = blockIdx.x & 3, win = blockIdx.x >> 2;
    int wh = win >> 4, ww = win & 15;
    int tid = threadIdx.x, wid = tid >> 5, lane = tid & 31;
    int gid = lane >> 2, tig = lane & 3;
    int wm = wid * 32;
    float scale = __expf(fminf(ls[h], LOG100));
    float shift = scale + 16.f;

    {
        int n = tid;
        int qrow = (wh * WS + (n >> 4)) * WIMG + ww * WS + (n & 15);
        const float4* src = (const float4*)(g_qkv + (size_t)qrow * QKVC + h * HD);
        float4 v[8]; float ss = 0.f;
        #pragma unroll
        for (int d = 0; d < 8; d++) {
            v[d] = src[d];
            ss += v[d].x*v[d].x + v[d].y*v[d].y + v[d].z*v[d].z + v[d].w*v[d].w;
        }
        float qi = scale / fmaxf(sqrtf(ss), 1e-12f);
        #pragma unroll
        for (int d = 0; d < 8; d++) {
            sQ[n][d*4+0] = f2tf32(v[d].x * qi);
            sQ[n][d*4+1] = f2tf32(v[d].y * qi);
            sQ[n][d*4+2] = f2tf32(v[d].z * qi);
            sQ[n][d*4+3] = f2tf32(v[d].w * qi);
        }
    }
    __syncthreads();

    uint32_t qf[4][2][4];
    #pragma unroll
    for (int kk = 0; kk < 4; kk++)
        #pragma unroll
        for (int mt = 0; mt < 2; mt++) {
            int r = wm + mt * 16;
            qf[kk][mt][0] = __float_as_uint(sQ[r + gid    ][kk*8 + tig    ]);
            qf[kk][mt][1] = __float_as_uint(sQ[r + gid + 8][kk*8 + tig    ]);
            qf[kk][mt][2] = __float_as_uint(sQ[r + gid    ][kk*8 + tig + 4]);
            qf[kk][mt][3] = __float_as_uint(sQ[r + gid + 8][kk*8 + tig + 4]);
        }

    float accO[2][4][4];
    #pragma unroll
    for (int mt = 0; mt < 2; mt++)
        #pragma unroll
        for (int nt = 0; nt < 4; nt++)
            #pragma unroll
            for (int r = 0; r < 4; r++) accO[mt][nt][r] = 0.f;
    float den[2][2] = {{0.f,0.f},{0.f,0.f}};

    for (int c = 0; c < 4; c++) {
        __syncthreads();
        if (tid < 64) {
            int m = c * 64 + tid;
            int krow = (wh * WS + (m >> 4)) * WIMG + ww * WS + (m & 15);
            const float4* src = (const float4*)(g_qkv + (size_t)krow * QKVC + 128 + h * HD);
            float4 v[8]; float ss = 0.f;
            #pragma unroll
            for (int d = 0; d < 8; d++) {
                v[d] = src[d];
                ss += v[d].x*v[d].x + v[d].y*v[d].y + v[d].z*v[d].z + v[d].w*v[d].w;
            }
            float ki = 1.f / fmaxf(sqrtf(ss), 1e-12f);
            #pragma unroll
            for (int d = 0; d < 8; d++) {
                sK[tid][d*4+0] = f2tf32(v[d].x * ki);
                sK[tid][d*4+1] = f2tf32(v[d].y * ki);
                sK[tid][d*4+2] = f2tf32(v[d].z * ki);
                sK[tid][d*4+3] = f2tf32(v[d].w * ki);
            }
        } else if (tid < 128) {
            int mm = tid - 64;
            int m = c * 64 + mm;
            int krow = (wh * WS + (m >> 4)) * WIMG + ww * WS + (m & 15);
            const float4* src = (const float4*)(g_qkv + (size_t)krow * QKVC + 256 + h * HD);
            #pragma unroll
            for (int d = 0; d < 8; d++) {
                float4 v = src[d];
                sV[mm][d*4+0] = f2tf32(v.x);
                sV[mm][d*4+1] = f2tf32(v.y);
                sV[mm][d*4+2] = f2tf32(v.z);
                sV[mm][d*4+3] = f2tf32(v.w);
            }
        }
        __syncthreads();

        float accS[2][8][4];
        #pragma unroll
        for (int mt = 0; mt < 2; mt++)
            #pragma unroll
            for (int nt = 0; nt < 8; nt++)
                #pragma unroll
                for (int r = 0; r < 4; r++) accS[mt][nt][r] = 0.f;

        #pragma unroll
        for (int kk = 0; kk < 4; kk++) {
            uint32_t bf[8][2];
            #pragma unroll
            for (int nt = 0; nt < 8; nt++) {
                int key = nt * 8 + gid;
                bf[nt][0] = __float_as_uint(sK[key][kk*8 + tig    ]);
                bf[nt][1] = __float_as_uint(sK[key][kk*8 + tig + 4]);
            }
            #pragma unroll
            for (int mt = 0; mt < 2; mt++)
                #pragma unroll
                for (int nt = 0; nt < 8; nt++)
                    mma_tf32(accS[mt][nt][0], accS[mt][nt][1], accS[mt][nt][2], accS[mt][nt][3],
                             qf[kk][mt][0], qf[kk][mt][1], qf[kk][mt][2], qf[kk][mt][3],
                             bf[nt][0], bf[nt][1]);
        }

        #pragma unroll
        for (int mt = 0; mt < 2; mt++) {
            int r_lo = wm + mt * 16 + gid, r_hi = r_lo + 8;
            const float* b_lo = g_biasw + ((size_t)h * NTOK_W + r_lo) * NTOK_W + c * 64 + tig * 2;
            const float* b_hi = g_biasw + ((size_t)h * NTOK_W + r_hi) * NTOK_W + c * 64 + tig * 2;
            #pragma unroll
            for (int nt = 0; nt < 8; nt++) {
                float2 bl = *(const float2*)(b_lo + nt * 8);
                float2 bh = *(const float2*)(b_hi + nt * 8);
                float p0 = __expf(accS[mt][nt][0] + bl.x - shift);
                float p1 = __expf(accS[mt][nt][1] + bl.y - shift);
                float p2 = __expf(accS[mt][nt][2] + bh.x - shift);
                float p3 = __expf(accS[mt][nt][3] + bh.y - shift);
                den[mt][0] += p0 + p1;
                den[mt][1] += p2 + p3;
                int col = nt * 8 + tig * 2;
                *(float2*)&sP[r_lo][col] = make_float2(f2tf32(p0), f2tf32(p1));
                *(float2*)&sP[r_hi][col] = make_float2(f2tf32(p2), f2tf32(p3));
            }
        }
        __syncwarp();

        #pragma unroll
        for (int kk2 = 0; kk2 < 8; kk2++) {
            uint32_t af[2][4];
            #pragma unroll
            for (int mt = 0; mt < 2; mt++) {
                int r = wm + mt * 16;
                af[mt][0] = __float_as_uint(sP[r + gid    ][kk2*8 + tig    ]);
                af[mt][1] = __float_as_uint(sP[r + gid + 8][kk2*8 + tig    ]);
                af[mt][2] = __float_as_uint(sP[r + gid    ][kk2*8 + tig + 4]);
                af[mt][3] = __float_as_uint(sP[r + gid + 8][kk2*8 + tig + 4]);
            }
            uint32_t vf[4][2];
            #pragma unroll
            for (int nt = 0; nt < 4; nt++) {
                int d = nt * 8 + gid;
                vf[nt][0] = __float_as_uint(sV[kk2*8 + tig    ][d]);
                vf[nt][1] = __float_as_uint(sV[kk2*8 + tig + 4][d]);
            }
            #pragma unroll
            for (int mt = 0; mt < 2; mt++)
                #pragma unroll
                for (int nt = 0; nt < 4; nt++)
                    mma_tf32(accO[mt][nt][0], accO[mt][nt][1], accO[mt][nt][2], accO[mt][nt][3],
                             af[mt][0], af[mt][1], af[mt][2], af[mt][3],
                             vf[nt][0], vf[nt][1]);
        }
    }

    #pragma unroll
    for (int mt = 0; mt < 2; mt++)
        #pragma unroll
        for (int j = 0; j < 2; j++) {
            den[mt][j] += __shfl_xor_sync(0xffffffffu, den[mt][j], 1);
            den[mt][j] += __shfl_xor_sync(0xffffffffu, den[mt][j], 2);
        }

    #pragma unroll
    for (int mt = 0; mt < 2; mt++) {
        int r_lo = wm + mt * 16 + gid, r_hi = r_lo + 8;
        float ri_lo = 1.f / den[mt][0], ri_hi = 1.f / den[mt][1];
        int qr_lo = (wh * WS + (r_lo >> 4)) * WIMG + ww * WS + (r_lo & 15);
        int qr_hi = (wh * WS + (r_hi >> 4)) * WIMG + ww * WS + (r_hi & 15);
        #pragma unroll
        for (int nt = 0; nt < 4; nt++) {
            int col = nt * 8 + tig * 2;
            *(float2*)&g_merged[(size_t)qr_lo * CDIM + h * HD + col] =
                make_float2(f2tf32(accO[mt][nt][0] * ri_lo), f2tf32(accO[mt][nt][1] * ri_lo));
            *(float2*)&g_merged[(size_t)qr_hi * CDIM + h * HD + col] =
                make_float2(f2tf32(accO[mt][nt][2] * ri_hi), f2tf32(accO[mt][nt][3] * ri_hi));
        }
    }
}

__global__ __launch_bounds__(128) void a1_attn_mma(const float* __restrict__ ls) {
    __shared__ float sQ[64][APAD];
    __shared__ float sK[64][APAD];
    __shared__ float sV[64][APAD];
    __shared__ float sP[64][PPAD];

    int h = blockIdx.x & 3, sidx = blockIdx.x >> 2;
    int sh = sidx >> 3, sw = sidx & 7;
    int tid = threadIdx.x, wid = tid >> 5, lane = tid & 31;
    int gid = lane >> 2, tig = lane & 3;
    int wm = wid * 16;
    float scale = __expf(fminf(ls[h], LOG100));
    float shift = scale + 16.f;

    if (tid < 64) {
        int ap = (sh * ASZ + (tid >> 3)) * AH + sw * ASZ + (tid & 7);
        const float4* src = (const float4*)(g_ancn + (size_t)ap * 128 + h * HD);
        #pragma unroll
        for (int d = 0; d < 8; d++) {
            float4 v = src[d];
            sQ[tid][d*4+0] = f2tf32(v.x * scale);
            sQ[tid][d*4+1] = f2tf32(v.y * scale);
            sQ[tid][d*4+2] = f2tf32(v.z * scale);
            sQ[tid][d*4+3] = f2tf32(v.w * scale);
        }
    }
    __syncthreads();

    uint32_t qf[4][4];
    #pragma unroll
    for (int kk = 0; kk < 4; kk++) {
        qf[kk][0] = __float_as_uint(sQ[wm + gid    ][kk*8 + tig    ]);
        qf[kk][1] = __float_as_uint(sQ[wm + gid + 8][kk*8 + tig    ]);
        qf[kk][2] = __float_as_uint(sQ[wm + gid    ][kk*8 + tig + 4]);
        qf[kk][3] = __float_as_uint(sQ[wm + gid + 8][kk*8 + tig + 4]);
    }

    float accO[4][4];
    #pragma unroll
    for (int nt = 0; nt < 4; nt++)
        #pragma unroll
        for (int r = 0; r < 4; r++) accO[nt][r] = 0.f;
    float den[2] = {0.f, 0.f};

    for (int c = 0; c < 16; c++) {
        __syncthreads();
        if (tid < 64) {
            int m = c * 64 + tid;
            int krow = (sh * SS + (m >> 5)) * WIMG + sw * SS + (m & 31);
            const float4* src = (const float4*)(g_qkv + (size_t)krow * QKVC + 512 + h * HD);
            float4 v[8]; float ss = 0.f;
            #pragma unroll
            for (int d = 0; d < 8; d++) {
                v[d] = src[d];
                ss += v[d].x*v[d].x + v[d].y*v[d].y + v[d].z*v[d].z + v[d].w*v[d].w;
            }
            float ki = 1.f / fmaxf(sqrtf(ss), 1e-12f);
            #pragma unroll
            for (int d = 0; d < 8; d++) {
                sK[tid][d*4+0] = f2tf32(v[d].x * ki);
                sK[tid][d*4+1] = f2tf32(v[d].y * ki);
                sK[tid][d*4+2] = f2tf32(v[d].z * ki);
                sK[tid][d*4+3] = f2tf32(v[d].w * ki);
            }
        } else {
            int mm = tid - 64;
            int m = c * 64 + mm;
            int krow = (sh * SS + (m >> 5)) * WIMG + sw * SS + (m & 31);
            const float4* src = (const float4*)(g_qkv + (size_t)krow * QKVC + 640 + h * HD);
            #pragma unroll
            for (int d = 0; d < 8; d++) {
                float4 v = src[d];
                sV[mm][d*4+0] = f2tf32(v.x);
                sV[mm][d*4+1] = f2tf32(v.y);
                sV[mm][d*4+2] = f2tf32(v.z);
                sV[mm][d*4+3] = f2tf32(v.w);
            }
        }
        __syncthreads();

        float accS[8][4];
        #pragma unroll
        for (int nt = 0; nt < 8; nt++)
            #pragma unroll
            for (int r = 0; r < 4; r++) accS[nt][r] = 0.f;

        #pragma unroll
        for (int kk = 0; kk < 4; kk++) {
            uint32_t bf[8][2];
            #pragma unroll
            for (int nt = 0; nt < 8; nt++) {
                int key = nt * 8 + gid;
                bf[nt][0] = __float_as_uint(sK[key][kk*8 + tig    ]);
                bf[nt][1] = __float_as_uint(sK[key][kk*8 + tig + 4]);
            }
            #pragma unroll
            for (int nt = 0; nt < 8; nt++)
                mma_tf32(accS[nt][0], accS[nt][1], accS[nt][2], accS[nt][3],
                         qf[kk][0], qf[kk][1], qf[kk][2], qf[kk][3],
                         bf[nt][0], bf[nt][1]);
        }

        {
            int r_lo = wm + gid, r_hi = r_lo + 8;
            const float* b_lo = g_biasa1 + ((size_t)h * NANC + r_lo) * NTOK_S + c * 64 + tig * 2;
            const float* b_hi = g_biasa1 + ((size_t)h * NANC + r_hi) * NTOK_S + c * 64 + tig * 2;
            #pragma unroll
            for (int nt = 0; nt < 8; nt++) {
                float2 bl = *(const float2*)(b_lo + nt * 8);
                float2 bh = *(const float2*)(b_hi + nt * 8);
                float p0 = __expf(accS[nt][0] + bl.x - shift);
                float p1 = __expf(accS[nt][1] + bl.y - shift);
                float p2 = __expf(accS[nt][2] + bh.x - shift);
                float p3 = __expf(accS[nt][3] + bh.y - shift);
                den[0] += p0 + p1;
                den[1] += p2 + p3;
                int col = nt * 8 + tig * 2;
                *(float2*)&sP[r_lo][col] = make_float2(f2tf32(p0), f2tf32(p1));
                *(float2*)&sP[r_hi][col] = make_float2(f2tf32(p2), f2tf32(p3));
            }
        }
        __syncwarp();

        #pragma unroll
        for (int kk2 = 0; kk2 < 8; kk2++) {
            uint32_t af[4];
            af[0] = __float_as_uint(sP[wm + gid    ][kk2*8 + tig    ]);
            af[1] = __float_as_uint(sP[wm + gid + 8][kk2*8 + tig    ]);
            af[2] = __float_as_uint(sP[wm + gid    ][kk2*8 + tig + 4]);
            af[3] = __float_as_uint(sP[wm + gid + 8][kk2*8 + tig + 4]);
            uint32_t vf[4][2];
            #pragma unroll
            for (int nt = 0; nt < 4; nt++) {
                int d = nt * 8 + gid;
                vf[nt][0] = __float_as_uint(sV[kk2*8 + tig    ][d]);
                vf[nt][1] = __float_as_uint(sV[kk2*8 + tig + 4][d]);
            }
            #pragma unroll
            for (int nt = 0; nt < 4; nt++)
                mma_tf32(accO[nt][0], accO[nt][1], accO[nt][2], accO[nt][3],
                         af[0], af[1], af[2], af[3], vf[nt][0], vf[nt][1]);
        }
    }

    #pragma unroll
    for (int j = 0; j < 2; j++) {
        den[j] += __shfl_xor_sync(0xffffffffu, den[j], 1);
        den[j] += __shfl_xor_sync(0xffffffffu, den[j], 2);
    }

    {
        int r_lo = wm + gid, r_hi = r_lo + 8;
        float ri_lo = 1.f / den[0], ri_hi = 1.f / den[1];
        float* o_lo = g_xm + (((size_t)sidx * NHEAD + h) * NANC + r_lo) * HD;
        float* o_hi = g_xm + (((size_t)sidx * NHEAD + h) * NANC + r_hi) * HD;
        #pragma unroll
        for (int nt = 0; nt < 4; nt++) {
            int col = nt * 8 + tig * 2;
            *(float2*)(o_lo + col) = make_float2(accO[nt][0] * ri_lo, accO[nt][1] * ri_lo);
            *(float2*)(o_hi + col) = make_float2(accO[nt][2] * ri_hi, accO[nt][3] * ri_hi);
        }
    }
}

__global__ __launch_bounds__(256) void a2_attn_mma(const float* __restrict__ ls) {
    extern __shared__ float sm[];
    float (*sQ)[APAD] = (float(*)[APAD])sm;
    float (*sK)[APAD] = (float(*)[APAD])(sm + 256 * APAD);
    float (*sV)[APAD] = (float(*)[APAD])(sm + 320 * APAD);
    float (*sP)[PPAD] = (float(*)[PPAD])(sm + 384 * APAD);

    int b = blockIdx.x;
    int qc = b & 3, h = (b >> 2) & 3, sidx = b >> 4;
    int sh = sidx >> 3, sw = sidx & 7;
    int tid = threadIdx.x, wid = tid >> 5, lane = tid & 31;
    int gid = lane >> 2, tig = lane & 3;
    int wm = wid * 32;
    float scale = __expf(fminf(ls[h], LOG100));
    float shift = scale + 16.f;

    {
        int n = qc * 256 + tid;
        int qrow = (sh * SS + (n >> 5)) * WIMG + sw * SS + (n & 31);
        const float4* src = (const float4*)(g_qkv + (size_t)qrow * QKVC + 384 + h * HD);
        float4 v[8]; float ss = 0.f;
        #pragma unroll
        for (int d = 0; d < 8; d++) {
            v[d] = src[d];
            ss += v[d].x*v[d].x + v[d].y*v[d].y + v[d].z*v[d].z + v[d].w*v[d].w;
        }
        float qi = scale / fmaxf(sqrtf(ss), 1e-12f);
        #pragma unroll
        for (int d = 0; d < 8; d++) {
            sQ[tid][d*4+0] = f2tf32(v[d].x * qi);
            sQ[tid][d*4+1] = f2tf32(v[d].y * qi);
            sQ[tid][d*4+2] = f2tf32(v[d].z * qi);
            sQ[tid][d*4+3] = f2tf32(v[d].w * qi);
        }
    }
    if (tid < 64) {
        int ap = (sh * ASZ + (tid >> 3)) * AH + sw * ASZ + (tid & 7);
        const float4* src = (const float4*)(g_ancn + (size_t)ap * 128 + h * HD);
        #pragma unroll
        for (int d = 0; d < 8; d++) {
            float4 v = src[d];
            sK[tid][d*4+0] = f2tf32(v.x); sK[tid][d*4+1] = f2tf32(v.y);
            sK[tid][d*4+2] = f2tf32(v.z); sK[tid][d*4+3] = f2tf32(v.w);
        }
    } else if (tid < 128) {
        int mm = tid - 64;
        const float4* src = (const float4*)(g_xm + (((size_t)sidx * NHEAD + h) * NANC + mm) * HD);
        #pragma unroll
        for (int d = 0; d < 8; d++) {
            float4 v = src[d];
            sV[mm][d*4+0] = f2tf32(v.x); sV[mm][d*4+1] = f2tf32(v.y);
            sV[mm][d*4+2] = f2tf32(v.z); sV[mm][d*4+3] = f2tf32(v.w);
        }
    }
    __syncthreads();

    uint32_t qf[4][2][4];
    #pragma unroll
    for (int kk = 0; kk < 4; kk++)
        #pragma unroll
        for (int mt = 0; mt < 2; mt++) {
            int r = wm + mt * 16;
            qf[kk][mt][0] = __float_as_uint(sQ[r + gid    ][kk*8 + tig    ]);
            qf[kk][mt][1] = __float_as_uint(sQ[r + gid + 8][kk*8 + tig    ]);
            qf[kk][mt][2] = __float_as_uint(sQ[r + gid    ][kk*8 + tig + 4]);
            qf[kk][mt][3] = __float_as_uint(sQ[r + gid + 8][kk*8 + tig + 4]);
        }

    float accS[2][8][4];
    #pragma unroll
    for (int mt = 0; mt < 2; mt++)
        #pragma unroll
        for (int nt = 0; nt < 8; nt++)
            #pragma unroll
            for (int r = 0; r < 4; r++) accS[mt][nt][r] = 0.f;

    #pragma unroll
    for (int kk = 0; kk < 4; kk++) {
        uint32_t bf[8][2];
        #pragma unroll
        for (int nt = 0; nt < 8; nt++) {
            int key = nt * 8 + gid;
            bf[nt][0] = __float_as_uint(sK[key][kk*8 + tig    ]);
            bf[nt][1] = __float_as_uint(sK[key][kk*8 + tig + 4]);
        }
        #pragma unroll
        for (int mt = 0; mt < 2; mt++)
            #pragma unroll
            for (int nt = 0; nt < 8; nt++)
                mma_tf32(accS[mt][nt][0], accS[mt][nt][1], accS[mt][nt][2], accS[mt][nt][3],
                         qf[kk][mt][0], qf[kk][mt][1], qf[kk][mt][2], qf[kk][mt][3],
                         bf[nt][0], bf[nt][1]);
    }

    float den[2][2] = {{0.f,0.f},{0.f,0.f}};
    #pragma unroll
    for (int mt = 0; mt < 2; mt++) {
        int r_lo = wm + mt * 16 + gid, r_hi = r_lo + 8;
        int n_lo = qc * 256 + r_lo, n_hi = qc * 256 + r_hi;
        const float* b_lo = g_biasw2a + ((size_t)h * NTOK_S + n_lo) * NANC + tig * 2;
        const float* b_hi = g_biasw2a + ((size_t)h * NTOK_S + n_hi) * NANC + tig * 2;
        #pragma unroll
        for (int nt = 0; nt < 8; nt++) {
            float2 bl = *(const float2*)(b_lo + nt * 8);
            float2 bh = *(const float2*)(b_hi + nt * 8);
            float p0 = __expf(accS[mt][nt][0] + bl.x - shift);
            float p1 = __expf(accS[mt][nt][1] + bl.y - shift);
            float p2 = __expf(accS[mt][nt][2] + bh.x - shift);
            float p3 = __expf(accS[mt][nt][3] + bh.y - shift);
            den[mt][0] += p0 + p1;
            den[mt][1] += p2 + p3;
            int col = nt * 8 + tig * 2;
            *(float2*)&sP[r_lo][col] = make_float2(f2tf32(p0), f2tf32(p1));
            *(float2*)&sP[r_hi][col] = make_float2(f2tf32(p2), f2tf32(p3));
        }
    }
    __syncwarp();

    float accO[2][4][4];
    #pragma unroll
    for (int mt = 0; mt < 2; mt++)
        #pragma unroll
        for (int nt = 0; nt < 4; nt++)
            #pragma unroll
            for (int r = 0; r < 4; r++) accO[mt][nt][r] = 0.f;

    #pragma unroll
    for (int kk2 = 0; kk2 < 8; kk2++) {
        uint32_t af[2][4];
        #pragma unroll
        for (int mt = 0; mt < 2; mt++) {
            int r = wm + mt * 16;
            af[mt][0] = __float_as_uint(sP[r + gid    ][kk2*8 + tig    ]);
            af[mt][1] = __float_as_uint(sP[r + gid + 8][kk2*8 + tig    ]);
            af[mt][2] = __float_as_uint(sP[r + gid    ][kk2*8 + tig + 4]);
            af[mt][3] = __float_as_uint(sP[r + gid + 8][kk2*8 + tig + 4]);
        }
        uint32_t vf[4][2];
        #pragma unroll
        for (int nt = 0; nt < 4; nt++) {
            int d = nt * 8 + gid;
            vf[nt][0] = __float_as_uint(sV[kk2*8 + tig    ][d]);
            vf[nt][1] = __float_as_uint(sV[kk2*8 + tig + 4][d]);
        }
        #pragma unroll
        for (int mt = 0; mt < 2; mt++)
            #pragma unroll
            for (int nt = 0; nt < 4; nt++)
                mma_tf32(accO[mt][nt][0], accO[mt][nt][1], accO[mt][nt][2], accO[mt][nt][3],
                         af[mt][0], af[mt][1], af[mt][2], af[mt][3],
                         vf[nt][0], vf[nt][1]);
    }

    #pragma unroll
    for (int mt = 0; mt < 2; mt++)
        #pragma unroll
        for (int j = 0; j < 2; j++) {
            den[mt][j] += __shfl_xor_sync(0xffffffffu, den[mt][j], 1);
            den[mt][j] += __shfl_xor_sync(0xffffffffu, den[mt][j], 2);
        }

    #pragma unroll
    for (int mt = 0; mt < 2; mt++) {
        int r_lo = wm + mt * 16 + gid, r_hi = r_lo + 8;
        int n_lo = qc * 256 + r_lo, n_hi = qc * 256 + r_hi;
        float ri_lo = 1.f / den[mt][0], ri_hi = 1.f / den[mt][1];
        int qr_lo = (sh * SS + (n_lo >> 5)) * WIMG + sw * SS + (n_lo & 31);
        int qr_hi = (sh * SS + (n_hi >> 5)) * WIMG + sw * SS + (n_hi & 31);
        #pragma unroll
        for (int nt = 0; nt < 4; nt++) {
            int col = nt * 8 + tig * 2;
            *(float2*)&g_merged[(size_t)qr_lo * CDIM + 128 + h * HD + col] =
                make_float2(f2tf32(accO[mt][nt][0] * ri_lo), f2tf32(accO[mt][nt][1] * ri_lo));
            *(float2*)&g_merged[(size_t)qr_hi * CDIM + 128 + h * HD + col] =
                make_float2(f2tf32(accO[mt][nt][2] * ri_hi), f2tf32(accO[mt][nt][3] * ri_hi));
        }
    }
}

// ---------------- launch ----------------
extern "C" void kernel_launch(void* const* d_in, const int* in_sizes, int n_in,
                              void* d_out, int out_size) {
    const float* x        = (const float*)d_in[0];
    const float* qkv_w    = (const float*)d_in[1];
    const float* qkv_b    = (const float*)d_in[2];
    const float* anchor_w = (const float*)d_in[3];
    const float* anchor_b = (const float*)d_in[4];
    const float* ls_w     = (const float*)d_in[5];
    const float* w1_w     = (const float*)d_in[6];
    const float* b1_w     = (const float*)d_in[7];
    const float* w2_w     = (const float*)d_in[8];
    const float* ls_s1    = (const float*)d_in[9];
    const float* w1_s1    = (const float*)d_in[10];
    const float* b1_s1    = (const float*)d_in[11];
    const float* w2_s1    = (const float*)d_in[12];
    const float* ls_s2    = (const float*)d_in[13];
    const float* w1_s2    = (const float*)d_in[14];
    const float* b1_s2    = (const float*)d_in[15];
    const float* w2_s2    = (const float*)d_in[16];
    const float* proj_w   = (const float*)d_in[17];
    const float* proj_b   = (const float*)d_in[18];
    const float* table_w  = (const float*)d_in[19];
    const float* table_s  = (const float*)d_in[20];
    const int*   index_w  = (const int*)d_in[21];
    const int*   index_a2w= (const int*)d_in[22];
    const int*   index_w2a= (const int*)d_in[23];
    float* out = (float*)d_out;

    float *p_qkv, *p_merged, *p_xr, *p_pooled, *p_anchor, *p_ancn;
    float *p_wqkv, *p_wanc, *p_wproj;
    float *p_btw, *p_bts1, *p_bts2, *p_biasw, *p_biasa1, *p_biasw2a;
    cudaGetSymbolAddress((void**)&p_qkv, g_qkv);
    cudaGetSymbolAddress((void**)&p_merged, g_merged);
    cudaGetSymbolAddress((void**)&p_xr, g_xr);
    cudaGetSymbolAddress((void**)&p_pooled, g_pooled);
    cudaGetSymbolAddress((void**)&p_anchor, g_anchor);
    cudaGetSymbolAddress((void**)&p_ancn, g_ancn);
    cudaGetSymbolAddress((void**)&p_wqkv, g_wqkv);
    cudaGetSymbolAddress((void**)&p_wanc, g_wanc);
    cudaGetSymbolAddress((void**)&p_wproj, g_wproj);
    cudaGetSymbolAddress((void**)&p_btw, g_btw);
    cudaGetSymbolAddress((void**)&p_bts1, g_bts1);
    cudaGetSymbolAddress((void**)&p_bts2, g_bts2);
    cudaGetSymbolAddress((void**)&p_biasw, g_biasw);
    cudaGetSymbolAddress((void**)&p_biasa1, g_biasa1);
    cudaGetSymbolAddress((void**)&p_biasw2a, g_biasw2a);

    static cudaStream_t s1 = 0, s2 = 0;
    static cudaEvent_t evP = 0, ev1 = 0, evS2 = 0;
    static bool init_done = false;
    if (!init_done) {
        cudaFuncSetAttribute(gemm_tf32, cudaFuncAttributeMaxDynamicSharedMemorySize, GEMM_SMEM_BYTES);
        cudaFuncSetAttribute(win_attn_mma, cudaFuncAttributeMaxDynamicSharedMemorySize, ATT_SMEM_BYTES);
        cudaFuncSetAttribute(a2_attn_mma, cudaFuncAttributeMaxDynamicSharedMemorySize, ATT_SMEM_BYTES);
        cudaStreamCreateWithFlags(&s1, cudaStreamNonBlocking);
        cudaStreamCreateWithFlags(&s2, cudaStreamNonBlocking);
        cudaEventCreateWithFlags(&evP, cudaEventDisableTiming);
        cudaEventCreateWithFlags(&ev1, cudaEventDisableTiming);
        cudaEventCreateWithFlags(&evS2, cudaEventDisableTiming);
        init_done = true;
    }

    // ---- phase 1 on main: weight rounding + x rounding, then fork ----
    round_weights<<<((CDIM*QKVC + CDIM*128 + CDIM*CDIM)/4 + 255) / 256, 256>>>(qkv_w, anchor_w, proj_w);
    round_tf32_vec<<<(LTOK * CDIM / 4 + 255) / 256, 256>>>(x, p_xr, LTOK * CDIM / 4);
    cudaEventRecord(evP, 0);

    // main: qkv half A (window branch, cols 0..383)
    gemm_tf32<<<dim3(3, LTOK / 128), 256, GEMM_SMEM_BYTES>>>(
        p_xr, p_wqkv, qkv_b, p_qkv, LTOK, QKVC, CDIM, 0);

    // s1: CPB MLPs + bias gathers (concurrent with qkv A)
    cudaStreamWaitEvent(s1, evP, 0);
    cpb_mlp3<<<dim3(12, 3), 128, 0, s1>>>(table_w, table_s,
                                          w1_w, b1_w, w2_w,
                                          w1_s1, b1_s1, w2_s1,
                                          w1_s2, b1_s2, w2_s2);
    gather_nat<<<(NHEAD * NTOK_W * NTOK_W + 255) / 256, 256, 0, s1>>>(p_btw, index_w, p_biasw, NTOK_W, NTOK_W);
    gather_nat<<<(NHEAD * NANC * NTOK_S + 255) / 256, 256, 0, s1>>>(p_bts1, index_a2w, p_biasa1, NANC, NTOK_S);
    gather_nat<<<(NHEAD * NTOK_S * NANC + 255) / 256, 256, 0, s1>>>(p_bts2, index_w2a, p_biasw2a, NTOK_S, NANC);
    cudaEventRecord(ev1, s1);

    // s2: anchor path, then qkv half B (stripe branch, cols 384..767), then a1->a2
    cudaStreamWaitEvent(s2, evP, 0);
    avgpool4<<<4096, 256, 0, s2>>>(x, p_pooled);
    gemm_tf32<<<dim3(1, 4096 / 128), 256, GEMM_SMEM_BYTES, s2>>>(p_pooled, p_wanc, anchor_b, p_anchor, 4096, 128, CDIM, 0);
    norm_anchor<<<(4096 * NHEAD + 255) / 256, 256, 0, s2>>>(p_anchor, p_ancn);
    gemm_tf32<<<dim3(3, LTOK / 128), 256, GEMM_SMEM_BYTES, s2>>>(
        p_xr, p_wqkv, qkv_b, p_qkv, LTOK, QKVC, CDIM, 384);   // base pointers; col_base does the offsetting
    cudaStreamWaitEvent(s2, ev1, 0);
    a1_attn_mma<<<64 * NHEAD, 128, 0, s2>>>(ls_s1);
    a2_attn_mma<<<64 * NHEAD * 4, 256, ATT_SMEM_BYTES, s2>>>(ls_s2);
    cudaEventRecord(evS2, s2);

    // main: window attention (starts right after qkv half A + gathers)
    cudaStreamWaitEvent(0, ev1, 0);
    win_attn_mma<<<256 * NHEAD, 256, ATT_SMEM_BYTES>>>(ls_w);

    // ---- output projection (needs both merged halves) ----
    cudaStreamWaitEvent(0, evS2, 0);
    gemm_tf32<<<dim3(CDIM / 128, LTOK / 128), 256, GEMM_SMEM_BYTES>>>(p_merged, p_wproj, proj_b, out, LTOK, CDIM, CDIM, 0);
}

// round 14
// speedup vs baseline: 1.1006x; 1.1006x over previous
#include <cuda_runtime.h>
#include <cuda_bf16.h>
#include <math.h>
#include <stdint.h>

// ---------------- problem constants ----------------
#define HIMG 256
#define WIMG 256
#define CDIM 256
#define LTOK (HIMG*WIMG)          // 65536
#define QKVC 768
#define NHEAD 4
#define HD 32
#define WS 16
#define NTOK_W 256
#define SS 32
#define NTOK_S 1024
#define ASZ 8
#define NANC 64
#define AH 64
#define TW_N 961
#define TS_N 1521
#define LOG100 4.60517018598809f

// ---------------- scratch (__device__ globals: no allocs allowed) ----------------
__device__ float g_qkv[(size_t)LTOK * QKVC];
__device__ float g_merged[(size_t)LTOK * CDIM];     // [xw | xs] tf32-rounded
__device__ float g_xr[(size_t)LTOK * CDIM];         // x tf32-rounded
__device__ float g_pooled[4096 * CDIM];
__device__ float g_anchor[4096 * 128];
__device__ float g_ancn[4096 * 128];
__device__ float g_xm[64 * NHEAD * NANC * HD];
__device__ float g_wqkv[CDIM * QKVC];
__device__ float g_wanc[CDIM * 128];
__device__ float g_wproj[CDIM * CDIM];
__device__ float g_btw[TW_N * NHEAD];
__device__ float g_bts1[TS_N * NHEAD];
__device__ float g_bts2[TS_N * NHEAD];
__device__ float g_biasw[NHEAD * NTOK_W * NTOK_W];    // [h][n][m]
__device__ float g_biasa1[NHEAD * NANC * NTOK_S];     // [h][n2=64][m=1024]
__device__ float g_biasw2a[NHEAD * NTOK_S * NANC];    // [h][n=1024][m=64]

// ---------------- helpers ----------------
__device__ __forceinline__ uint32_t f2tf32u(float x) {
    uint32_t u;
    asm("cvt.rna.tf32.f32 %0, %1;" : "=r"(u) : "f"(x));
    return u;
}
__device__ __forceinline__ float f2tf32(float x) { return __uint_as_float(f2tf32u(x)); }

__device__ __forceinline__ void mma_tf32(float& c0, float& c1, float& c2, float& c3,
                                         uint32_t a0, uint32_t a1, uint32_t a2, uint32_t a3,
                                         uint32_t b0, uint32_t b1) {
    asm volatile(
        "mma.sync.aligned.m16n8k8.row.col.f32.tf32.tf32.f32 "
        "{%0,%1,%2,%3}, {%4,%5,%6,%7}, {%8,%9}, {%0,%1,%2,%3};"
        : "+f"(c0), "+f"(c1), "+f"(c2), "+f"(c3)
        : "r"(a0), "r"(a1), "r"(a2), "r"(a3), "r"(b0), "r"(b1));
}

__device__ __forceinline__ void cp16(void* smem_dst, const void* gsrc) {
    uint32_t s = (uint32_t)__cvta_generic_to_shared(smem_dst);
    asm volatile("cp.async.cg.shared.global [%0], [%1], 16;" :: "r"(s), "l"(gsrc));
}
__device__ __forceinline__ void cp_commit() { asm volatile("cp.async.commit_group;"); }
template<int N> __device__ __forceinline__ void cp_wait() {
    asm volatile("cp.async.wait_group %0;" :: "n"(N));
}

// ---------------- rounding kernels ----------------
__global__ void round_tf32_vec(const float* __restrict__ in, float* __restrict__ out, int n4) {
    int i = blockIdx.x * blockDim.x + threadIdx.x;
    if (i >= n4) return;
    float4 v = ((const float4*)in)[i];
    v.x = f2tf32(v.x); v.y = f2tf32(v.y); v.z = f2tf32(v.z); v.w = f2tf32(v.w);
    ((float4*)out)[i] = v;
}

__global__ void round_weights(const float* __restrict__ qkv_w,
                              const float* __restrict__ anchor_w,
                              const float* __restrict__ proj_w) {
    int i = blockIdx.x * blockDim.x + threadIdx.x;
    int n_qkv = CDIM * QKVC / 4, n_anc = CDIM * 128 / 4, n_proj = CDIM * CDIM / 4;
    const float4* src; float4* dst; int idx;
    if (i < n_qkv) { src = (const float4*)qkv_w; dst = (float4*)g_wqkv; idx = i; }
    else if (i < n_qkv + n_anc) { src = (const float4*)anchor_w; dst = (float4*)g_wanc; idx = i - n_qkv; }
    else if (i < n_qkv + n_anc + n_proj) { src = (const float4*)proj_w; dst = (float4*)g_wproj; idx = i - n_qkv - n_anc; }
    else return;
    float4 v = src[idx];
    v.x = f2tf32(v.x); v.y = f2tf32(v.y); v.z = f2tf32(v.z); v.w = f2tf32(v.w);
    dst[idx] = v;
}

// ---------------- tf32 tensor-core GEMM, cp.async 3-stage ----------------
#define GEMM_SMEM_BYTES (3*(128*36 + 32*136)*4)
__global__ __launch_bounds__(256) void gemm_tf32(const float* __restrict__ A,
                                                 const float* __restrict__ B,
                                                 const float* __restrict__ bias,
                                                 float* __restrict__ C,
                                                 int M, int N, int K) {
    extern __shared__ float smem[];
    float (*As)[128][36] = (float(*)[128][36])smem;
    float (*Bs)[32][136] = (float(*)[32][136])(smem + 3 * 128 * 36);

    int tid = threadIdx.x;
    int wid = tid >> 5;
    int lane = tid & 31;
    int gid = lane >> 2;
    int tig = lane & 3;
    int wm = (wid >> 2) * 64;
    int wn = (wid & 3) * 32;

    int row0 = blockIdx.y * 128;
    int col0 = blockIdx.x * 128;

    float acc[4][4][4];
    #pragma unroll
    for (int mt = 0; mt < 4; mt++)
        #pragma unroll
        for (int nt = 0; nt < 4; nt++)
            #pragma unroll
            for (int r = 0; r < 4; r++) acc[mt][nt][r] = 0.f;

    auto load_tile = [&](int st, int k0) {
        #pragma unroll
        for (int i = 0; i < 4; i++) {
            int f = tid + i * 256;
            int r = f >> 3, c4 = (f & 7) << 2;
            cp16(&As[st][r][c4], &A[(size_t)(row0 + r) * K + k0 + c4]);
        }
        #pragma unroll
        for (int i = 0; i < 4; i++) {
            int f = tid + i * 256;
            int r = f >> 5, c4 = (f & 31) << 2;
            cp16(&Bs[st][r][c4], &B[(size_t)(k0 + r) * N + col0 + c4]);
        }
        cp_commit();
    };

    int nk = K >> 5;
    load_tile(0, 0);
    if (nk > 1) load_tile(1, 32);
    for (int it = 0; it < nk; it++) {
        int st = it % 3;
        if (it + 2 < nk) { load_tile((it + 2) % 3, (it + 2) << 5); cp_wait<2>(); }
        else if (it + 1 < nk) cp_wait<1>();
        else cp_wait<0>();
        __syncthreads();

        #pragma unroll
        for (int kk = 0; kk < 32; kk += 8) {
            uint32_t af[4][4];
            #pragma unroll
            for (int mt = 0; mt < 4; mt++) {
                int rbase = wm + mt * 16;
                af[mt][0] = __float_as_uint(As[st][rbase + gid    ][kk + tig    ]);
                af[mt][1] = __float_as_uint(As[st][rbase + gid + 8][kk + tig    ]);
                af[mt][2] = __float_as_uint(As[st][rbase + gid    ][kk + tig + 4]);
                af[mt][3] = __float_as_uint(As[st][rbase + gid + 8][kk + tig + 4]);
            }
            uint32_t bf[4][2];
            #pragma unroll
            for (int nt = 0; nt < 4; nt++) {
                int cbase = wn + nt * 8 + gid;
                bf[nt][0] = __float_as_uint(Bs[st][kk + tig    ][cbase]);
                bf[nt][1] = __float_as_uint(Bs[st][kk + tig + 4][cbase]);
            }
            #pragma unroll
            for (int mt = 0; mt < 4; mt++)
                #pragma unroll
                for (int nt = 0; nt < 4; nt++)
                    mma_tf32(acc[mt][nt][0], acc[mt][nt][1], acc[mt][nt][2], acc[mt][nt][3],
                             af[mt][0], af[mt][1], af[mt][2], af[mt][3],
                             bf[nt][0], bf[nt][1]);
        }
        __syncthreads();
    }

    #pragma unroll
    for (int nt = 0; nt < 4; nt++) {
        int col = col0 + wn + nt * 8 + tig * 2;
        float b0 = bias[col], b1 = bias[col + 1];
        #pragma unroll
        for (int mt = 0; mt < 4; mt++) {
            int row = row0 + wm + mt * 16 + gid;
            float2 o0 = make_float2(acc[mt][nt][0] + b0, acc[mt][nt][1] + b1);
            float2 o1 = make_float2(acc[mt][nt][2] + b0, acc[mt][nt][3] + b1);
            *(float2*)&C[(size_t)row * N + col] = o0;
            *(float2*)&C[(size_t)(row + 8) * N + col] = o1;
        }
    }
}

// ---------------- CPB MLPs batched ----------------
__global__ void cpb_mlp3(const float* __restrict__ tw, const float* __restrict__ ts,
                         const float* __restrict__ w1a, const float* __restrict__ b1a,
                         const float* __restrict__ w2a,
                         const float* __restrict__ w1b, const float* __restrict__ b1b,
                         const float* __restrict__ w2b,
                         const float* __restrict__ w1c, const float* __restrict__ b1c,
                         const float* __restrict__ w2c) {
    int set = blockIdx.y;
    const float* table = (set == 0) ? tw : ts;
    int T = (set == 0) ? TW_N : TS_N;
    const float* w1 = (set == 0) ? w1a : (set == 1) ? w1b : w1c;
    const float* b1 = (set == 0) ? b1a : (set == 1) ? b1b : b1c;
    const float* w2 = (set == 0) ? w2a : (set == 1) ? w2b : w2c;
    float* bt = (set == 0) ? g_btw : (set == 1) ? g_bts1 : g_bts2;

    __shared__ float s_w1[1024];
    __shared__ float s_b1[512];
    __shared__ float s_w2[2048];
    for (int i = threadIdx.x; i < 1024; i += blockDim.x) s_w1[i] = w1[i];
    for (int i = threadIdx.x; i < 512;  i += blockDim.x) s_b1[i] = b1[i];
    for (int i = threadIdx.x; i < 2048; i += blockDim.x) s_w2[i] = w2[i];
    __syncthreads();
    int t = blockIdx.x * blockDim.x + threadIdx.x;
    if (t >= T) return;
    float t0 = table[t * 2], t1 = table[t * 2 + 1];
    float a0 = 0.f, a1 = 0.f, a2 = 0.f, a3 = 0.f;
    for (int j = 0; j < 512; j++) {
        float hsum = fmaf(t0, s_w1[j], fmaf(t1, s_w1[512 + j], s_b1[j]));
        float hr = fmaxf(hsum, 0.f);
        a0 = fmaf(hr, s_w2[j * 4 + 0], a0);
        a1 = fmaf(hr, s_w2[j * 4 + 1], a1);
        a2 = fmaf(hr, s_w2[j * 4 + 2], a2);
        a3 = fmaf(hr, s_w2[j * 4 + 3], a3);
    }
    bt[t * 4 + 0] = a0; bt[t * 4 + 1] = a1; bt[t * 4 + 2] = a2; bt[t * 4 + 3] = a3;
}

// ---------------- natural-layout gather [h][n][m] ----------------
__global__ void gather_nat(const float* __restrict__ bt, const int* __restrict__ index,
                           float* __restrict__ out, int Nq, int Nk) {
    int i = blockIdx.x * blockDim.x + threadIdx.x;
    int total = NHEAD * Nq * Nk;
    if (i >= total) return;
    int m = i % Nk;
    int n = (i / Nk) % Nq;
    int h = i / (Nk * Nq);
    int id = index[n * Nk + m];
    float b = bt[id * 4 + h];
    out[i] = 16.f / (1.f + __expf(-b));   // out[h][n][m]
}

// ---------------- avg pool 4x4 (tf32-rounded output) ----------------
__global__ void avgpool4(const float* __restrict__ x, float* __restrict__ pooled) {
    int p = blockIdx.x;
    int ch = threadIdx.x;
    int ph = p >> 6, pw = p & 63;
    float s = 0.f;
    #pragma unroll
    for (int i = 0; i < 4; i++)
        #pragma unroll
        for (int j = 0; j < 4; j++)
            s += x[((size_t)((ph * 4 + i) * WIMG + pw * 4 + j)) * CDIM + ch];
    pooled[(size_t)p * CDIM + ch] = f2tf32(s * 0.0625f);
}

// ---------------- anchor l2 normalize ----------------
__global__ void norm_anchor(const float* __restrict__ a, float* __restrict__ an) {
    int i = blockIdx.x * blockDim.x + threadIdx.x;
    if (i >= 4096 * NHEAD) return;
    int p = i >> 2, h = i & 3;
    const float4* src = (const float4*)(a + (size_t)p * 128 + h * HD);
    float4 v[8];
    float ss = 0.f;
    #pragma unroll
    for (int d = 0; d < 8; d++) {
        v[d] = src[d];
        ss += v[d].x * v[d].x + v[d].y * v[d].y + v[d].z * v[d].z + v[d].w * v[d].w;
    }
    float inv = 1.f / fmaxf(sqrtf(ss), 1e-12f);
    float4* dst = (float4*)(an + (size_t)p * 128 + h * HD);
    #pragma unroll
    for (int d = 0; d < 8; d++) {
        v[d].x *= inv; v[d].y *= inv; v[d].z *= inv; v[d].w *= inv;
        dst[d] = v[d];
    }
}

// =========================================================================
// Tensor-core flash attention — 128-thread / 64-query CTAs (a1's shape)
// static smem 45 KB -> 4-5 CTAs/SM, 16-20 warps/SM
// =========================================================================
#define APAD 36
#define PPAD 68

// ---- window attention: 64-query chunk x 4 chunks of 64 keys ----
__global__ __launch_bounds__(128) void win_attn_mma(const float* __restrict__ ls) {
    __shared__ float sQ[64][APAD];
    __shared__ float sK[64][APAD];
    __shared__ float sV[64][APAD];
    __shared__ float sP[64][PPAD];

    int b = blockIdx.x;
    int qc = b & 3, h = (b >> 2) & 3, win = b >> 4;
    int wh = win >> 4, ww = win & 15;
    int tid = threadIdx.x, wid = tid >> 5, lane = tid & 31;
    int gid = lane >> 2, tig = lane & 3;
    int wm = wid * 16;
    float scale = __expf(fminf(ls[h], LOG100));
    float shift = scale + 16.f;

    if (tid < 64) {
        int n = qc * 64 + tid;
        int qrow = (wh * WS + (n >> 4)) * WIMG + ww * WS + (n & 15);
        const float4* src = (const float4*)(g_qkv + (size_t)qrow * QKVC + h * HD);
        float4 v[8]; float ss = 0.f;
        #pragma unroll
        for (int d = 0; d < 8; d++) {
            v[d] = src[d];
            ss += v[d].x*v[d].x + v[d].y*v[d].y + v[d].z*v[d].z + v[d].w*v[d].w;
        }
        float qi = scale / fmaxf(sqrtf(ss), 1e-12f);
        #pragma unroll
        for (int d = 0; d < 8; d++) {
            sQ[tid][d*4+0] = f2tf32(v[d].x * qi);
            sQ[tid][d*4+1] = f2tf32(v[d].y * qi);
            sQ[tid][d*4+2] = f2tf32(v[d].z * qi);
            sQ[tid][d*4+3] = f2tf32(v[d].w * qi);
        }
    }
    __syncthreads();

    uint32_t qf[4][4];
    #pragma unroll
    for (int kk = 0; kk < 4; kk++) {
        qf[kk][0] = __float_as_uint(sQ[wm + gid    ][kk*8 + tig    ]);
        qf[kk][1] = __float_as_uint(sQ[wm + gid + 8][kk*8 + tig    ]);
        qf[kk][2] = __float_as_uint(sQ[wm + gid    ][kk*8 + tig + 4]);
        qf[kk][3] = __float_as_uint(sQ[wm + gid + 8][kk*8 + tig + 4]);
    }

    float accO[4][4];
    #pragma unroll
    for (int nt = 0; nt < 4; nt++)
        #pragma unroll
        for (int r = 0; r < 4; r++) accO[nt][r] = 0.f;
    float den[2] = {0.f, 0.f};

    for (int c = 0; c < 4; c++) {
        __syncthreads();
        if (tid < 64) {
            int m = c * 64 + tid;
            int krow = (wh * WS + (m >> 4)) * WIMG + ww * WS + (m & 15);
            const float4* src = (const float4*)(g_qkv + (size_t)krow * QKVC + 128 + h * HD);
            float4 v[8]; float ss = 0.f;
            #pragma unroll
            for (int d = 0; d < 8; d++) {
                v[d] = src[d];
                ss += v[d].x*v[d].x + v[d].y*v[d].y + v[d].z*v[d].z + v[d].w*v[d].w;
            }
            float ki = 1.f / fmaxf(sqrtf(ss), 1e-12f);
            #pragma unroll
            for (int d = 0; d < 8; d++) {
                sK[tid][d*4+0] = f2tf32(v[d].x * ki);
                sK[tid][d*4+1] = f2tf32(v[d].y * ki);
                sK[tid][d*4+2] = f2tf32(v[d].z * ki);
                sK[tid][d*4+3] = f2tf32(v[d].w * ki);
            }
        } else {
            int mm = tid - 64;
            int m = c * 64 + mm;
            int krow = (wh * WS + (m >> 4)) * WIMG + ww * WS + (m & 15);
            const float4* src = (const float4*)(g_qkv + (size_t)krow * QKVC + 256 + h * HD);
            #pragma unroll
            for (int d = 0; d < 8; d++) {
                float4 v = src[d];
                sV[mm][d*4+0] = f2tf32(v.x);
                sV[mm][d*4+1] = f2tf32(v.y);
                sV[mm][d*4+2] = f2tf32(v.z);
                sV[mm][d*4+3] = f2tf32(v.w);
            }
        }
        __syncthreads();

        float accS[8][4];
        #pragma unroll
        for (int nt = 0; nt < 8; nt++)
            #pragma unroll
            for (int r = 0; r < 4; r++) accS[nt][r] = 0.f;

        #pragma unroll
        for (int kk = 0; kk < 4; kk++) {
            uint32_t bf[8][2];
            #pragma unroll
            for (int nt = 0; nt < 8; nt++) {
                int key = nt * 8 + gid;
                bf[nt][0] = __float_as_uint(sK[key][kk*8 + tig    ]);
                bf[nt][1] = __float_as_uint(sK[key][kk*8 + tig + 4]);
            }
            #pragma unroll
            for (int nt = 0; nt < 8; nt++)
                mma_tf32(accS[nt][0], accS[nt][1], accS[nt][2], accS[nt][3],
                         qf[kk][0], qf[kk][1], qf[kk][2], qf[kk][3],
                         bf[nt][0], bf[nt][1]);
        }

        {
            int r_lo = wm + gid, r_hi = r_lo + 8;
            int n_lo = qc * 64 + r_lo, n_hi = qc * 64 + r_hi;
            const float* b_lo = g_biasw + ((size_t)h * NTOK_W + n_lo) * NTOK_W + c * 64 + tig * 2;
            const float* b_hi = g_biasw + ((size_t)h * NTOK_W + n_hi) * NTOK_W + c * 64 + tig * 2;
            #pragma unroll
            for (int nt = 0; nt < 8; nt++) {
                float2 bl = *(const float2*)(b_lo + nt * 8);
                float2 bh = *(const float2*)(b_hi + nt * 8);
                float p0 = __expf(accS[nt][0] + bl.x - shift);
                float p1 = __expf(accS[nt][1] + bl.y - shift);
                float p2 = __expf(accS[nt][2] + bh.x - shift);
                float p3 = __expf(accS[nt][3] + bh.y - shift);
                den[0] += p0 + p1;
                den[1] += p2 + p3;
                int col = nt * 8 + tig * 2;
                *(float2*)&sP[r_lo][col] = make_float2(f2tf32(p0), f2tf32(p1));
                *(float2*)&sP[r_hi][col] = make_float2(f2tf32(p2), f2tf32(p3));
            }
        }
        __syncwarp();

        #pragma unroll
        for (int kk2 = 0; kk2 < 8; kk2++) {
            uint32_t af[4];
            af[0] = __float_as_uint(sP[wm + gid    ][kk2*8 + tig    ]);
            af[1] = __float_as_uint(sP[wm + gid + 8][kk2*8 + tig    ]);
            af[2] = __float_as_uint(sP[wm + gid    ][kk2*8 + tig + 4]);
            af[3] = __float_as_uint(sP[wm + gid + 8][kk2*8 + tig + 4]);
            uint32_t vf[4][2];
            #pragma unroll
            for (int nt = 0; nt < 4; nt++) {
                int d = nt * 8 + gid;
                vf[nt][0] = __float_as_uint(sV[kk2*8 + tig    ][d]);
                vf[nt][1] = __float_as_uint(sV[kk2*8 + tig + 4][d]);
            }
            #pragma unroll
            for (int nt = 0; nt < 4; nt++)
                mma_tf32(accO[nt][0], accO[nt][1], accO[nt][2], accO[nt][3],
                         af[0], af[1], af[2], af[3], vf[nt][0], vf[nt][1]);
        }
    }

    #pragma unroll
    for (int j = 0; j < 2; j++) {
        den[j] += __shfl_xor_sync(0xffffffffu, den[j], 1);
        den[j] += __shfl_xor_sync(0xffffffffu, den[j], 2);
    }

    {
        int r_lo = wm + gid, r_hi = r_lo + 8;
        int n_lo = qc * 64 + r_lo, n_hi = qc * 64 + r_hi;
        float ri_lo = 1.f / den[0], ri_hi = 1.f / den[1];
        int qr_lo = (wh * WS + (n_lo >> 4)) * WIMG + ww * WS + (n_lo & 15);
        int qr_hi = (wh * WS + (n_hi >> 4)) * WIMG + ww * WS + (n_hi & 15);
        #pragma unroll
        for (int nt = 0; nt < 4; nt++) {
            int col = nt * 8 + tig * 2;
            *(float2*)&g_merged[(size_t)qr_lo * CDIM + h * HD + col] =
                make_float2(f2tf32(accO[nt][0] * ri_lo), f2tf32(accO[nt][1] * ri_lo));
            *(float2*)&g_merged[(size_t)qr_hi * CDIM + h * HD + col] =
                make_float2(f2tf32(accO[nt][2] * ri_hi), f2tf32(accO[nt][3] * ri_hi));
        }
    }
}

// ---- a1: 64 anchor queries x 16 chunks of 64 stripe keys -> xm (unchanged) ----
__global__ __launch_bounds__(128) void a1_attn_mma(const float* __restrict__ ls) {
    __shared__ float sQ[64][APAD];
    __shared__ float sK[64][APAD];
    __shared__ float sV[64][APAD];
    __shared__ float sP[64][PPAD];

    int h = blockIdx.x & 3, sidx = blockIdx.x >> 2;
    int sh = sidx >> 3, sw = sidx & 7;
    int tid = threadIdx.x, wid = tid >> 5, lane = tid & 31;
    int gid = lane >> 2, tig = lane & 3;
    int wm = wid * 16;
    float scale = __expf(fminf(ls[h], LOG100));
    float shift = scale + 16.f;

    if (tid < 64) {
        int ap = (sh * ASZ + (tid >> 3)) * AH + sw * ASZ + (tid & 7);
        const float4* src = (const float4*)(g_ancn + (size_t)ap * 128 + h * HD);
        #pragma unroll
        for (int d = 0; d < 8; d++) {
            float4 v = src[d];
            sQ[tid][d*4+0] = f2tf32(v.x * scale);
            sQ[tid][d*4+1] = f2tf32(v.y * scale);
            sQ[tid][d*4+2] = f2tf32(v.z * scale);
            sQ[tid][d*4+3] = f2tf32(v.w * scale);
        }
    }
    __syncthreads();

    uint32_t qf[4][4];
    #pragma unroll
    for (int kk = 0; kk < 4; kk++) {
        qf[kk][0] = __float_as_uint(sQ[wm + gid    ][kk*8 + tig    ]);
        qf[kk][1] = __float_as_uint(sQ[wm + gid + 8][kk*8 + tig    ]);
        qf[kk][2] = __float_as_uint(sQ[wm + gid    ][kk*8 + tig + 4]);
        qf[kk][3] = __float_as_uint(sQ[wm + gid + 8][kk*8 + tig + 4]);
    }

    float accO[4][4];
    #pragma unroll
    for (int nt = 0; nt < 4; nt++)
        #pragma unroll
        for (int r = 0; r < 4; r++) accO[nt][r] = 0.f;
    float den[2] = {0.f, 0.f};

    for (int c = 0; c < 16; c++) {
        __syncthreads();
        if (tid < 64) {
            int m = c * 64 + tid;
            int krow = (sh * SS + (m >> 5)) * WIMG + sw * SS + (m & 31);
            const float4* src = (const float4*)(g_qkv + (size_t)krow * QKVC + 512 + h * HD);
            float4 v[8]; float ss = 0.f;
            #pragma unroll
            for (int d = 0; d < 8; d++) {
                v[d] = src[d];
                ss += v[d].x*v[d].x + v[d].y*v[d].y + v[d].z*v[d].z + v[d].w*v[d].w;
            }
            float ki = 1.f / fmaxf(sqrtf(ss), 1e-12f);
            #pragma unroll
            for (int d = 0; d < 8; d++) {
                sK[tid][d*4+0] = f2tf32(v[d].x * ki);
                sK[tid][d*4+1] = f2tf32(v[d].y * ki);
                sK[tid][d*4+2] = f2tf32(v[d].z * ki);
                sK[tid][d*4+3] = f2tf32(v[d].w * ki);
            }
        } else {
            int mm = tid - 64;
            int m = c * 64 + mm;
            int krow = (sh * SS + (m >> 5)) * WIMG + sw * SS + (m & 31);
            const float4* src = (const float4*)(g_qkv + (size_t)krow * QKVC + 640 + h * HD);
            #pragma unroll
            for (int d = 0; d < 8; d++) {
                float4 v = src[d];
                sV[mm][d*4+0] = f2tf32(v.x);
                sV[mm][d*4+1] = f2tf32(v.y);
                sV[mm][d*4+2] = f2tf32(v.z);
                sV[mm][d*4+3] = f2tf32(v.w);
            }
        }
        __syncthreads();

        float accS[8][4];
        #pragma unroll
        for (int nt = 0; nt < 8; nt++)
            #pragma unroll
            for (int r = 0; r < 4; r++) accS[nt][r] = 0.f;

        #pragma unroll
        for (int kk = 0; kk < 4; kk++) {
            uint32_t bf[8][2];
            #pragma unroll
            for (int nt = 0; nt < 8; nt++) {
                int key = nt * 8 + gid;
                bf[nt][0] = __float_as_uint(sK[key][kk*8 + tig    ]);
                bf[nt][1] = __float_as_uint(sK[key][kk*8 + tig + 4]);
            }
            #pragma unroll
            for (int nt = 0; nt < 8; nt++)
                mma_tf32(accS[nt][0], accS[nt][1], accS[nt][2], accS[nt][3],
                         qf[kk][0], qf[kk][1], qf[kk][2], qf[kk][3],
                         bf[nt][0], bf[nt][1]);
        }

        {
            int r_lo = wm + gid, r_hi = r_lo + 8;
            const float* b_lo = g_biasa1 + ((size_t)h * NANC + r_lo) * NTOK_S + c * 64 + tig * 2;
            const float* b_hi = g_biasa1 + ((size_t)h * NANC + r_hi) * NTOK_S + c * 64 + tig * 2;
            #pragma unroll
            for (int nt = 0; nt < 8; nt++) {
                float2 bl = *(const float2*)(b_lo + nt * 8);
                float2 bh = *(const float2*)(b_hi + nt * 8);
                float p0 = __expf(accS[nt][0] + bl.x - shift);
                float p1 = __expf(accS[nt][1] + bl.y - shift);
                float p2 = __expf(accS[nt][2] + bh.x - shift);
                float p3 = __expf(accS[nt][3] + bh.y - shift);
                den[0] += p0 + p1;
                den[1] += p2 + p3;
                int col = nt * 8 + tig * 2;
                *(float2*)&sP[r_lo][col] = make_float2(f2tf32(p0), f2tf32(p1));
                *(float2*)&sP[r_hi][col] = make_float2(f2tf32(p2), f2tf32(p3));
            }
        }
        __syncwarp();

        #pragma unroll
        for (int kk2 = 0; kk2 < 8; kk2++) {
            uint32_t af[4];
            af[0] = __float_as_uint(sP[wm + gid    ][kk2*8 + tig    ]);
            af[1] = __float_as_uint(sP[wm + gid + 8][kk2*8 + tig    ]);
            af[2] = __float_as_uint(sP[wm + gid    ][kk2*8 + tig + 4]);
            af[3] = __float_as_uint(sP[wm + gid + 8][kk2*8 + tig + 4]);
            uint32_t vf[4][2];
            #pragma unroll
            for (int nt = 0; nt < 4; nt++) {
                int d = nt * 8 + gid;
                vf[nt][0] = __float_as_uint(sV[kk2*8 + tig    ][d]);
                vf[nt][1] = __float_as_uint(sV[kk2*8 + tig + 4][d]);
            }
            #pragma unroll
            for (int nt = 0; nt < 4; nt++)
                mma_tf32(accO[nt][0], accO[nt][1], accO[nt][2], accO[nt][3],
                         af[0], af[1], af[2], af[3], vf[nt][0], vf[nt][1]);
        }
    }

    #pragma unroll
    for (int j = 0; j < 2; j++) {
        den[j] += __shfl_xor_sync(0xffffffffu, den[j], 1);
        den[j] += __shfl_xor_sync(0xffffffffu, den[j], 2);
    }

    {
        int r_lo = wm + gid, r_hi = r_lo + 8;
        float ri_lo = 1.f / den[0], ri_hi = 1.f / den[1];
        float* o_lo = g_xm + (((size_t)sidx * NHEAD + h) * NANC + r_lo) * HD;
        float* o_hi = g_xm + (((size_t)sidx * NHEAD + h) * NANC + r_hi) * HD;
        #pragma unroll
        for (int nt = 0; nt < 4; nt++) {
            int col = nt * 8 + tig * 2;
            *(float2*)(o_lo + col) = make_float2(accO[nt][0] * ri_lo, accO[nt][1] * ri_lo);
            *(float2*)(o_hi + col) = make_float2(accO[nt][2] * ri_hi, accO[nt][3] * ri_hi);
        }
    }
}

// ---- a2: 64-query chunk x 64 anchors (V = xm), 128 threads ----
__global__ __launch_bounds__(128) void a2_attn_mma(const float* __restrict__ ls) {
    __shared__ float sQ[64][APAD];
    __shared__ float sK[64][APAD];
    __shared__ float sV[64][APAD];
    __shared__ float sP[64][PPAD];

    int b = blockIdx.x;
    int qc = b & 15, h = (b >> 4) & 3, sidx = b >> 6;
    int sh = sidx >> 3, sw = sidx & 7;
    int tid = threadIdx.x, wid = tid >> 5, lane = tid & 31;
    int gid = lane >> 2, tig = lane & 3;
    int wm = wid * 16;
    float scale = __expf(fminf(ls[h], LOG100));
    float shift = scale + 16.f;

    if (tid < 64) {
        // Q row
        int n = qc * 64 + tid;
        int qrow = (sh * SS + (n >> 5)) * WIMG + sw * SS + (n & 31);
        const float4* src = (const float4*)(g_qkv + (size_t)qrow * QKVC + 384 + h * HD);
        float4 v[8]; float ss = 0.f;
        #pragma unroll
        for (int d = 0; d < 8; d++) {
            v[d] = src[d];
            ss += v[d].x*v[d].x + v[d].y*v[d].y + v[d].z*v[d].z + v[d].w*v[d].w;
        }
        float qi = scale / fmaxf(sqrtf(ss), 1e-12f);
        #pragma unroll
        for (int d = 0; d < 8; d++) {
            sQ[tid][d*4+0] = f2tf32(v[d].x * qi);
            sQ[tid][d*4+1] = f2tf32(v[d].y * qi);
            sQ[tid][d*4+2] = f2tf32(v[d].z * qi);
            sQ[tid][d*4+3] = f2tf32(v[d].w * qi);
        }
        // K = anchors (already normalized)
        int ap = (sh * ASZ + (tid >> 3)) * AH + sw * ASZ + (tid & 7);
        const float4* ksrc = (const float4*)(g_ancn + (size_t)ap * 128 + h * HD);
        #pragma unroll
        for (int d = 0; d < 8; d++) {
            float4 v2 = ksrc[d];
            sK[tid][d*4+0] = f2tf32(v2.x); sK[tid][d*4+1] = f2tf32(v2.y);
            sK[tid][d*4+2] = f2tf32(v2.z); sK[tid][d*4+3] = f2tf32(v2.w);
        }
    } else {
        int mm = tid - 64;
        const float4* src = (const float4*)(g_xm + (((size_t)sidx * NHEAD + h) * NANC + mm) * HD);
        #pragma unroll
        for (int d = 0; d < 8; d++) {
            float4 v = src[d];
            sV[mm][d*4+0] = f2tf32(v.x); sV[mm][d*4+1] = f2tf32(v.y);
            sV[mm][d*4+2] = f2tf32(v.z); sV[mm][d*4+3] = f2tf32(v.w);
        }
    }
    __syncthreads();

    uint32_t qf[4][4];
    #pragma unroll
    for (int kk = 0; kk < 4; kk++) {
        qf[kk][0] = __float_as_uint(sQ[wm + gid    ][kk*8 + tig    ]);
        qf[kk][1] = __float_as_uint(sQ[wm + gid + 8][kk*8 + tig    ]);
        qf[kk][2] = __float_as_uint(sQ[wm + gid    ][kk*8 + tig + 4]);
        qf[kk][3] = __float_as_uint(sQ[wm + gid + 8][kk*8 + tig + 4]);
    }

    float accS[8][4];
    #pragma unroll
    for (int nt = 0; nt < 8; nt++)
        #pragma unroll
        for (int r = 0; r < 4; r++) accS[nt][r] = 0.f;

    #pragma unroll
    for (int kk = 0; kk < 4; kk++) {
        uint32_t bf[8][2];
        #pragma unroll
        for (int nt = 0; nt < 8; nt++) {
            int key = nt * 8 + gid;
            bf[nt][0] = __float_as_uint(sK[key][kk*8 + tig    ]);
            bf[nt][1] = __float_as_uint(sK[key][kk*8 + tig + 4]);
        }
        #pragma unroll
        for (int nt = 0; nt < 8; nt++)
            mma_tf32(accS[nt][0], accS[nt][1], accS[nt][2], accS[nt][3],
                     qf[kk][0], qf[kk][1], qf[kk][2], qf[kk][3],
                     bf[nt][0], bf[nt][1]);
    }

    float den[2] = {0.f, 0.f};
    {
        int r_lo = wm + gid, r_hi = r_lo + 8;
        int n_lo = qc * 64 + r_lo, n_hi = qc * 64 + r_hi;
        const float* b_lo = g_biasw2a + ((size_t)h * NTOK_S + n_lo) * NANC + tig * 2;
        const float* b_hi = g_biasw2a + ((size_t)h * NTOK_S + n_hi) * NANC + tig * 2;
        #pragma unroll
        for (int nt = 0; nt < 8; nt++) {
            float2 bl = *(const float2*)(b_lo + nt * 8);
            float2 bh = *(const float2*)(b_hi + nt * 8);
            float p0 = __expf(accS[nt][0] + bl.x - shift);
            float p1 = __expf(accS[nt][1] + bl.y - shift);
            float p2 = __expf(accS[nt][2] + bh.x - shift);
            float p3 = __expf(accS[nt][3] + bh.y - shift);
            den[0] += p0 + p1;
            den[1] += p2 + p3;
            int col = nt * 8 + tig * 2;
            *(float2*)&sP[r_lo][col] = make_float2(f2tf32(p0), f2tf32(p1));
            *(float2*)&sP[r_hi][col] = make_float2(f2tf32(p2), f2tf32(p3));
        }
    }
    __syncwarp();

    float accO[4][4];
    #pragma unroll
    for (int nt = 0; nt < 4; nt++)
        #pragma unroll
        for (int r = 0; r < 4; r++) accO[nt][r] = 0.f;

    #pragma unroll
    for (int kk2 = 0; kk2 < 8; kk2++) {
        uint32_t af[4];
        af[0] = __float_as_uint(sP[wm + gid    ][kk2*8 + tig    ]);
        af[1] = __float_as_uint(sP[wm + gid + 8][kk2*8 + tig    ]);
        af[2] = __float_as_uint(sP[wm + gid    ][kk2*8 + tig + 4]);
        af[3] = __float_as_uint(sP[wm + gid + 8][kk2*8 + tig + 4]);
        uint32_t vf[4][2];
        #pragma unroll
        for (int nt = 0; nt < 4; nt++) {
            int d = nt * 8 + gid;
            vf[nt][0] = __float_as_uint(sV[kk2*8 + tig    ][d]);
            vf[nt][1] = __float_as_uint(sV[kk2*8 + tig + 4][d]);
        }
        #pragma unroll
        for (int nt = 0; nt < 4; nt++)
            mma_tf32(accO[nt][0], accO[nt][1], accO[nt][2], accO[nt][3],
                     af[0], af[1], af[2], af[3], vf[nt][0], vf[nt][1]);
    }

    #pragma unroll
    for (int j = 0; j < 2; j++) {
        den[j] += __shfl_xor_sync(0xffffffffu, den[j], 1);
        den[j] += __shfl_xor_sync(0xffffffffu, den[j], 2);
    }

    {
        int r_lo = wm + gid, r_hi = r_lo + 8;
        int n_lo = qc * 64 + r_lo, n_hi = qc * 64 + r_hi;
        float ri_lo = 1.f / den[0], ri_hi = 1.f / den[1];
        int qr_lo = (sh * SS + (n_lo >> 5)) * WIMG + sw * SS + (n_lo & 31);
        int qr_hi = (sh * SS + (n_hi >> 5)) * WIMG + sw * SS + (n_hi & 31);
        #pragma unroll
        for (int nt = 0; nt < 4; nt++) {
            int col = nt * 8 + tig * 2;
            *(float2*)&g_merged[(size_t)qr_lo * CDIM + 128 + h * HD + col] =
                make_float2(f2tf32(accO[nt][0] * ri_lo), f2tf32(accO[nt][1] * ri_lo));
            *(float2*)&g_merged[(size_t)qr_hi * CDIM + 128 + h * HD + col] =
                make_float2(f2tf32(accO[nt][2] * ri_hi), f2tf32(accO[nt][3] * ri_hi));
        }
    }
}

// ---------------- launch (exact R6 DAG) ----------------
extern "C" void kernel_launch(void* const* d_in, const int* in_sizes, int n_in,
                              void* d_out, int out_size) {
    const float* x        = (const float*)d_in[0];
    const float* qkv_w    = (const float*)d_in[1];
    const float* qkv_b    = (const float*)d_in[2];
    const float* anchor_w = (const float*)d_in[3];
    const float* anchor_b = (const float*)d_in[4];
    const float* ls_w     = (const float*)d_in[5];
    const float* w1_w     = (const float*)d_in[6];
    const float* b1_w     = (const float*)d_in[7];
    const float* w2_w     = (const float*)d_in[8];
    const float* ls_s1    = (const float*)d_in[9];
    const float* w1_s1    = (const float*)d_in[10];
    const float* b1_s1    = (const float*)d_in[11];
    const float* w2_s1    = (const float*)d_in[12];
    const float* ls_s2    = (const float*)d_in[13];
    const float* w1_s2    = (const float*)d_in[14];
    const float* b1_s2    = (const float*)d_in[15];
    const float* w2_s2    = (const float*)d_in[16];
    const float* proj_w   = (const float*)d_in[17];
    const float* proj_b   = (const float*)d_in[18];
    const float* table_w  = (const float*)d_in[19];
    const float* table_s  = (const float*)d_in[20];
    const int*   index_w  = (const int*)d_in[21];
    const int*   index_a2w= (const int*)d_in[22];
    const int*   index_w2a= (const int*)d_in[23];
    float* out = (float*)d_out;

    float *p_qkv, *p_merged, *p_xr, *p_pooled, *p_anchor, *p_ancn;
    float *p_wqkv, *p_wanc, *p_wproj;
    float *p_btw, *p_bts1, *p_bts2, *p_biasw, *p_biasa1, *p_biasw2a;
    cudaGetSymbolAddress((void**)&p_qkv, g_qkv);
    cudaGetSymbolAddress((void**)&p_merged, g_merged);
    cudaGetSymbolAddress((void**)&p_xr, g_xr);
    cudaGetSymbolAddress((void**)&p_pooled, g_pooled);
    cudaGetSymbolAddress((void**)&p_anchor, g_anchor);
    cudaGetSymbolAddress((void**)&p_ancn, g_ancn);
    cudaGetSymbolAddress((void**)&p_wqkv, g_wqkv);
    cudaGetSymbolAddress((void**)&p_wanc, g_wanc);
    cudaGetSymbolAddress((void**)&p_wproj, g_wproj);
    cudaGetSymbolAddress((void**)&p_btw, g_btw);
    cudaGetSymbolAddress((void**)&p_bts1, g_bts1);
    cudaGetSymbolAddress((void**)&p_bts2, g_bts2);
    cudaGetSymbolAddress((void**)&p_biasw, g_biasw);
    cudaGetSymbolAddress((void**)&p_biasa1, g_biasa1);
    cudaGetSymbolAddress((void**)&p_biasw2a, g_biasw2a);

    static cudaStream_t s1 = 0, s2 = 0;
    static cudaEvent_t evW = 0, ev1 = 0, ev2 = 0, evQ = 0, ev3 = 0;
    static bool init_done = false;
    if (!init_done) {
        cudaFuncSetAttribute(gemm_tf32, cudaFuncAttributeMaxDynamicSharedMemorySize, GEMM_SMEM_BYTES);
        cudaStreamCreateWithFlags(&s1, cudaStreamNonBlocking);
        cudaStreamCreateWithFlags(&s2, cudaStreamNonBlocking);
        cudaEventCreateWithFlags(&evW, cudaEventDisableTiming);
        cudaEventCreateWithFlags(&ev1, cudaEventDisableTiming);
        cudaEventCreateWithFlags(&ev2, cudaEventDisableTiming);
        cudaEventCreateWithFlags(&evQ, cudaEventDisableTiming);
        cudaEventCreateWithFlags(&ev3, cudaEventDisableTiming);
        init_done = true;
    }

    // ---- phase 1: weight rounding on main stream, fork side streams ----
    round_weights<<<((CDIM*QKVC + CDIM*128 + CDIM*CDIM)/4 + 255) / 256, 256>>>(qkv_w, anchor_w, proj_w);
    cudaEventRecord(evW, 0);

    // s1: CPB MLPs + bias gathers
    cudaStreamWaitEvent(s1, evW, 0);
    cpb_mlp3<<<dim3(12, 3), 128, 0, s1>>>(table_w, table_s,
                                          w1_w, b1_w, w2_w,
                                          w1_s1, b1_s1, w2_s1,
                                          w1_s2, b1_s2, w2_s2);
    gather_nat<<<(NHEAD * NTOK_W * NTOK_W + 255) / 256, 256, 0, s1>>>(p_btw, index_w, p_biasw, NTOK_W, NTOK_W);
    gather_nat<<<(NHEAD * NANC * NTOK_S + 255) / 256, 256, 0, s1>>>(p_bts1, index_a2w, p_biasa1, NANC, NTOK_S);
    gather_nat<<<(NHEAD * NTOK_S * NANC + 255) / 256, 256, 0, s1>>>(p_bts2, index_w2a, p_biasw2a, NTOK_S, NANC);
    cudaEventRecord(ev1, s1);

    // s2: anchor path
    cudaStreamWaitEvent(s2, evW, 0);
    avgpool4<<<4096, 256, 0, s2>>>(x, p_pooled);
    gemm_tf32<<<dim3(1, 4096 / 128), 256, GEMM_SMEM_BYTES, s2>>>(p_pooled, p_wanc, anchor_b, p_anchor, 4096, 128, CDIM);
    norm_anchor<<<(4096 * NHEAD + 255) / 256, 256, 0, s2>>>(p_anchor, p_ancn);
    cudaEventRecord(ev2, s2);

    // main: x rounding + qkv GEMM
    round_tf32_vec<<<(LTOK * CDIM / 4 + 255) / 256, 256>>>(x, p_xr, LTOK * CDIM / 4);
    gemm_tf32<<<dim3(QKVC / 128, LTOK / 128), 256, GEMM_SMEM_BYTES>>>(
        p_xr, p_wqkv, qkv_b, p_qkv, LTOK, QKVC, CDIM);

    // join
    cudaStreamWaitEvent(0, ev1, 0);
    cudaStreamWaitEvent(0, ev2, 0);
    cudaEventRecord(evQ, 0);

    // ---- phase 2: attention; win on main, a1->a2 chain on s1 ----
    cudaStreamWaitEvent(s1, evQ, 0);
    a1_attn_mma<<<64 * NHEAD, 128, 0, s1>>>(ls_s1);
    a2_attn_mma<<<64 * NHEAD * 16, 128, 0, s1>>>(ls_s2);
    cudaEventRecord(ev3, s1);

    win_attn_mma<<<256 * NHEAD * 4, 128>>>(ls_w);

    cudaStreamWaitEvent(0, ev3, 0);

    // ---- phase 3: output projection ----
    gemm_tf32<<<dim3(CDIM / 128, LTOK / 128), 256, GEMM_SMEM_BYTES>>>(p_merged, p_wproj, proj_b, out, LTOK, CDIM, CDIM);
}

// round 15
// speedup vs baseline: 1.2079x; 1.0975x over previous
#include <cuda_runtime.h>
#include <cuda_bf16.h>
#include <math.h>
#include <stdint.h>

// ---------------- problem constants ----------------
#define HIMG 256
#define WIMG 256
#define CDIM 256
#define LTOK (HIMG*WIMG)          // 65536
#define QKVC 768
#define NHEAD 4
#define HD 32
#define WS 16
#define NTOK_W 256
#define SS 32
#define NTOK_S 1024
#define ASZ 8
#define NANC 64
#define AH 64
#define TW_N 961
#define TS_N 1521
#define LOG100 4.60517018598809f

// ---------------- scratch (__device__ globals: no allocs allowed) ----------------
__device__ float g_qkv[(size_t)LTOK * QKVC];
__device__ float g_merged[(size_t)LTOK * CDIM];     // [xw | xs] tf32-rounded
__device__ float g_xr[(size_t)LTOK * CDIM];         // x tf32-rounded
__device__ float g_pooled[4096 * CDIM];
__device__ float g_anchor[4096 * 128];
__device__ float g_ancn[4096 * 128];
__device__ float g_xm[64 * NHEAD * NANC * HD];
__device__ float g_wqkv[CDIM * QKVC];
__device__ float g_wanc[CDIM * 128];
__device__ float g_wproj[CDIM * CDIM];
__device__ float g_btw[TW_N * NHEAD];
__device__ float g_bts1[TS_N * NHEAD];
__device__ float g_bts2[TS_N * NHEAD];
__device__ float g_biasw[NHEAD * NTOK_W * NTOK_W];    // [h][n][m]
__device__ float g_biasa1[NHEAD * NANC * NTOK_S];     // [h][n2=64][m=1024]
__device__ float g_biasw2a[NHEAD * NTOK_S * NANC];    // [h][n=1024][m=64]

// ---------------- helpers ----------------
__device__ __forceinline__ uint32_t f2tf32u(float x) {
    uint32_t u;
    asm("cvt.rna.tf32.f32 %0, %1;" : "=r"(u) : "f"(x));
    return u;
}
__device__ __forceinline__ float f2tf32(float x) { return __uint_as_float(f2tf32u(x)); }

__device__ __forceinline__ void mma_tf32(float& c0, float& c1, float& c2, float& c3,
                                         uint32_t a0, uint32_t a1, uint32_t a2, uint32_t a3,
                                         uint32_t b0, uint32_t b1) {
    asm volatile(
        "mma.sync.aligned.m16n8k8.row.col.f32.tf32.tf32.f32 "
        "{%0,%1,%2,%3}, {%4,%5,%6,%7}, {%8,%9}, {%0,%1,%2,%3};"
        : "+f"(c0), "+f"(c1), "+f"(c2), "+f"(c3)
        : "r"(a0), "r"(a1), "r"(a2), "r"(a3), "r"(b0), "r"(b1));
}

__device__ __forceinline__ void cp16(void* smem_dst, const void* gsrc) {
    uint32_t s = (uint32_t)__cvta_generic_to_shared(smem_dst);
    asm volatile("cp.async.cg.shared.global [%0], [%1], 16;" :: "r"(s), "l"(gsrc));
}
__device__ __forceinline__ void cp_commit() { asm volatile("cp.async.commit_group;"); }
template<int N> __device__ __forceinline__ void cp_wait() {
    asm volatile("cp.async.wait_group %0;" :: "n"(N));
}

// ---------------- rounding kernels ----------------
__global__ void round_tf32_vec(const float* __restrict__ in, float* __restrict__ out, int n4) {
    int i = blockIdx.x * blockDim.x + threadIdx.x;
    if (i >= n4) return;
    float4 v = ((const float4*)in)[i];
    v.x = f2tf32(v.x); v.y = f2tf32(v.y); v.z = f2tf32(v.z); v.w = f2tf32(v.w);
    ((float4*)out)[i] = v;
}

__global__ void round_weights(const float* __restrict__ qkv_w,
                              const float* __restrict__ anchor_w,
                              const float* __restrict__ proj_w) {
    int i = blockIdx.x * blockDim.x + threadIdx.x;
    int n_qkv = CDIM * QKVC / 4, n_anc = CDIM * 128 / 4, n_proj = CDIM * CDIM / 4;
    const float4* src; float4* dst; int idx;
    if (i < n_qkv) { src = (const float4*)qkv_w; dst = (float4*)g_wqkv; idx = i; }
    else if (i < n_qkv + n_anc) { src = (const float4*)anchor_w; dst = (float4*)g_wanc; idx = i - n_qkv; }
    else if (i < n_qkv + n_anc + n_proj) { src = (const float4*)proj_w; dst = (float4*)g_wproj; idx = i - n_qkv - n_anc; }
    else return;
    float4 v = src[idx];
    v.x = f2tf32(v.x); v.y = f2tf32(v.y); v.z = f2tf32(v.z); v.w = f2tf32(v.w);
    dst[idx] = v;
}

// ---------------- tf32 tensor-core GEMM, cp.async 3-stage ----------------
#define GEMM_SMEM_BYTES (3*(128*36 + 32*136)*4)
__global__ __launch_bounds__(256) void gemm_tf32(const float* __restrict__ A,
                                                 const float* __restrict__ B,
                                                 const float* __restrict__ bias,
                                                 float* __restrict__ C,
                                                 int M, int N, int K) {
    extern __shared__ float smem[];
    float (*As)[128][36] = (float(*)[128][36])smem;
    float (*Bs)[32][136] = (float(*)[32][136])(smem + 3 * 128 * 36);

    int tid = threadIdx.x;
    int wid = tid >> 5;
    int lane = tid & 31;
    int gid = lane >> 2;
    int tig = lane & 3;
    int wm = (wid >> 2) * 64;
    int wn = (wid & 3) * 32;

    int row0 = blockIdx.y * 128;
    int col0 = blockIdx.x * 128;

    float acc[4][4][4];
    #pragma unroll
    for (int mt = 0; mt < 4; mt++)
        #pragma unroll
        for (int nt = 0; nt < 4; nt++)
            #pragma unroll
            for (int r = 0; r < 4; r++) acc[mt][nt][r] = 0.f;

    auto load_tile = [&](int st, int k0) {
        #pragma unroll
        for (int i = 0; i < 4; i++) {
            int f = tid + i * 256;
            int r = f >> 3, c4 = (f & 7) << 2;
            cp16(&As[st][r][c4], &A[(size_t)(row0 + r) * K + k0 + c4]);
        }
        #pragma unroll
        for (int i = 0; i < 4; i++) {
            int f = tid + i * 256;
            int r = f >> 5, c4 = (f & 31) << 2;
            cp16(&Bs[st][r][c4], &B[(size_t)(k0 + r) * N + col0 + c4]);
        }
        cp_commit();
    };

    int nk = K >> 5;
    load_tile(0, 0);
    if (nk > 1) load_tile(1, 32);
    for (int it = 0; it < nk; it++) {
        int st = it % 3;
        if (it + 2 < nk) { load_tile((it + 2) % 3, (it + 2) << 5); cp_wait<2>(); }
        else if (it + 1 < nk) cp_wait<1>();
        else cp_wait<0>();
        __syncthreads();

        #pragma unroll
        for (int kk = 0; kk < 32; kk += 8) {
            uint32_t af[4][4];
            #pragma unroll
            for (int mt = 0; mt < 4; mt++) {
                int rbase = wm + mt * 16;
                af[mt][0] = __float_as_uint(As[st][rbase + gid    ][kk + tig    ]);
                af[mt][1] = __float_as_uint(As[st][rbase + gid + 8][kk + tig    ]);
                af[mt][2] = __float_as_uint(As[st][rbase + gid    ][kk + tig + 4]);
                af[mt][3] = __float_as_uint(As[st][rbase + gid + 8][kk + tig + 4]);
            }
            uint32_t bf[4][2];
            #pragma unroll
            for (int nt = 0; nt < 4; nt++) {
                int cbase = wn + nt * 8 + gid;
                bf[nt][0] = __float_as_uint(Bs[st][kk + tig    ][cbase]);
                bf[nt][1] = __float_as_uint(Bs[st][kk + tig + 4][cbase]);
            }
            #pragma unroll
            for (int mt = 0; mt < 4; mt++)
                #pragma unroll
                for (int nt = 0; nt < 4; nt++)
                    mma_tf32(acc[mt][nt][0], acc[mt][nt][1], acc[mt][nt][2], acc[mt][nt][3],
                             af[mt][0], af[mt][1], af[mt][2], af[mt][3],
                             bf[nt][0], bf[nt][1]);
        }
        __syncthreads();
    }

    #pragma unroll
    for (int nt = 0; nt < 4; nt++) {
        int col = col0 + wn + nt * 8 + tig * 2;
        float b0 = bias[col], b1 = bias[col + 1];
        #pragma unroll
        for (int mt = 0; mt < 4; mt++) {
            int row = row0 + wm + mt * 16 + gid;
            float2 o0 = make_float2(acc[mt][nt][0] + b0, acc[mt][nt][1] + b1);
            float2 o1 = make_float2(acc[mt][nt][2] + b0, acc[mt][nt][3] + b1);
            *(float2*)&C[(size_t)row * N + col] = o0;
            *(float2*)&C[(size_t)(row + 8) * N + col] = o1;
        }
    }
}

// ---------------- CPB MLPs batched ----------------
__global__ void cpb_mlp3(const float* __restrict__ tw, const float* __restrict__ ts,
                         const float* __restrict__ w1a, const float* __restrict__ b1a,
                         const float* __restrict__ w2a,
                         const float* __restrict__ w1b, const float* __restrict__ b1b,
                         const float* __restrict__ w2b,
                         const float* __restrict__ w1c, const float* __restrict__ b1c,
                         const float* __restrict__ w2c) {
    int set = blockIdx.y;
    const float* table = (set == 0) ? tw : ts;
    int T = (set == 0) ? TW_N : TS_N;
    const float* w1 = (set == 0) ? w1a : (set == 1) ? w1b : w1c;
    const float* b1 = (set == 0) ? b1a : (set == 1) ? b1b : b1c;
    const float* w2 = (set == 0) ? w2a : (set == 1) ? w2b : w2c;
    float* bt = (set == 0) ? g_btw : (set == 1) ? g_bts1 : g_bts2;

    __shared__ float s_w1[1024];
    __shared__ float s_b1[512];
    __shared__ float s_w2[2048];
    for (int i = threadIdx.x; i < 1024; i += blockDim.x) s_w1[i] = w1[i];
    for (int i = threadIdx.x; i < 512;  i += blockDim.x) s_b1[i] = b1[i];
    for (int i = threadIdx.x; i < 2048; i += blockDim.x) s_w2[i] = w2[i];
    __syncthreads();
    int t = blockIdx.x * blockDim.x + threadIdx.x;
    if (t >= T) return;
    float t0 = table[t * 2], t1 = table[t * 2 + 1];
    float a0 = 0.f, a1 = 0.f, a2 = 0.f, a3 = 0.f;
    for (int j = 0; j < 512; j++) {
        float hsum = fmaf(t0, s_w1[j], fmaf(t1, s_w1[512 + j], s_b1[j]));
        float hr = fmaxf(hsum, 0.f);
        a0 = fmaf(hr, s_w2[j * 4 + 0], a0);
        a1 = fmaf(hr, s_w2[j * 4 + 1], a1);
        a2 = fmaf(hr, s_w2[j * 4 + 2], a2);
        a3 = fmaf(hr, s_w2[j * 4 + 3], a3);
    }
    bt[t * 4 + 0] = a0; bt[t * 4 + 1] = a1; bt[t * 4 + 2] = a2; bt[t * 4 + 3] = a3;
}

// ---------------- natural-layout gather [h][n][m] ----------------
__global__ void gather_nat(const float* __restrict__ bt, const int* __restrict__ index,
                           float* __restrict__ out, int Nq, int Nk) {
    int i = blockIdx.x * blockDim.x + threadIdx.x;
    int total = NHEAD * Nq * Nk;
    if (i >= total) return;
    int m = i % Nk;
    int n = (i / Nk) % Nq;
    int h = i / (Nk * Nq);
    int id = index[n * Nk + m];
    float b = bt[id * 4 + h];
    out[i] = 16.f / (1.f + __expf(-b));   // out[h][n][m]
}

// ---------------- avg pool 4x4 (tf32-rounded output) ----------------
__global__ void avgpool4(const float* __restrict__ x, float* __restrict__ pooled) {
    int p = blockIdx.x;
    int ch = threadIdx.x;
    int ph = p >> 6, pw = p & 63;
    float s = 0.f;
    #pragma unroll
    for (int i = 0; i < 4; i++)
        #pragma unroll
        for (int j = 0; j < 4; j++)
            s += x[((size_t)((ph * 4 + i) * WIMG + pw * 4 + j)) * CDIM + ch];
    pooled[(size_t)p * CDIM + ch] = f2tf32(s * 0.0625f);
}

// ---------------- anchor l2 normalize ----------------
__global__ void norm_anchor(const float* __restrict__ a, float* __restrict__ an) {
    int i = blockIdx.x * blockDim.x + threadIdx.x;
    if (i >= 4096 * NHEAD) return;
    int p = i >> 2, h = i & 3;
    const float4* src = (const float4*)(a + (size_t)p * 128 + h * HD);
    float4 v[8];
    float ss = 0.f;
    #pragma unroll
    for (int d = 0; d < 8; d++) {
        v[d] = src[d];
        ss += v[d].x * v[d].x + v[d].y * v[d].y + v[d].z * v[d].z + v[d].w * v[d].w;
    }
    float inv = 1.f / fmaxf(sqrtf(ss), 1e-12f);
    float4* dst = (float4*)(an + (size_t)p * 128 + h * HD);
    #pragma unroll
    for (int d = 0; d < 8; d++) {
        v[d].x *= inv; v[d].y *= inv; v[d].z *= inv; v[d].w *= inv;
        dst[d] = v[d];
    }
}

// =========================================================================
// Tensor-core flash attention
// =========================================================================
#define APAD 36
#define PPAD 68
// a2 layout (R6): sQ 256*36 | sK 64*36 | sV 64*36 | sP 256*68
#define ATT_SMEM_FLOATS (256*APAD + 64*APAD + 64*APAD + 256*PPAD)
#define ATT_SMEM_BYTES (ATT_SMEM_FLOATS*4)
// win layout: above + cp.async stage [2 bufs][K|V][64][36]
#define WIN_SMEM_FLOATS (ATT_SMEM_FLOATS + 4*64*APAD)
#define WIN_SMEM_BYTES (WIN_SMEM_FLOATS*4)

// ---- window attention: 256 queries x 4 chunks of 64 keys, K/V cp.async pipelined ----
__global__ __launch_bounds__(256) void win_attn_mma(const float* __restrict__ ls) {
    extern __shared__ float sm[];
    float (*sQ)[APAD] = (float(*)[APAD])sm;
    float (*sK)[APAD] = (float(*)[APAD])(sm + 256 * APAD);
    float (*sV)[APAD] = (float(*)[APAD])(sm + 320 * APAD);
    float (*sP)[PPAD] = (float(*)[PPAD])(sm + 384 * APAD);
    float* stage = sm + 384 * APAD + 256 * PPAD;       // [st][half][64][36]

    int h = blockIdx.x & 3, win = blockIdx.x >> 2;
    int wh = win >> 4, ww = win & 15;
    int tid = threadIdx.x, wid = tid >> 5, lane = tid & 31;
    int gid = lane >> 2, tig = lane & 3;
    int wm = wid * 32;
    float scale = __expf(fminf(ls[h], LOG100));
    float shift = scale + 16.f;

    // issue prefetch of chunk 0 BEFORE the Q phase so it overlaps Q work
    auto prefetch = [&](int st, int c) {
        #pragma unroll
        for (int i = 0; i < 4; i++) {
            int f = tid + i * 256;           // 0..1023: 512 K-f4 + 512 V-f4
            int half = f >> 9;
            int idx = f & 511;
            int row = idx >> 3, c4 = (idx & 7) * 4;
            int m = c * 64 + row;
            int krow = (wh * WS + (m >> 4)) * WIMG + ww * WS + (m & 15);
            const float* src = g_qkv + (size_t)krow * QKVC + 128 + half * 128 + h * HD + c4;
            float* dst = stage + ((st * 2 + half) * 64 + row) * APAD + c4;
            cp16(dst, src);
        }
        cp_commit();
    };
    prefetch(0, 0);

    {
        int n = tid;
        int qrow = (wh * WS + (n >> 4)) * WIMG + ww * WS + (n & 15);
        const float4* src = (const float4*)(g_qkv + (size_t)qrow * QKVC + h * HD);
        float4 v[8]; float ss = 0.f;
        #pragma unroll
        for (int d = 0; d < 8; d++) {
            v[d] = src[d];
            ss += v[d].x*v[d].x + v[d].y*v[d].y + v[d].z*v[d].z + v[d].w*v[d].w;
        }
        float qi = scale / fmaxf(sqrtf(ss), 1e-12f);
        #pragma unroll
        for (int d = 0; d < 8; d++) {
            sQ[n][d*4+0] = f2tf32(v[d].x * qi);
            sQ[n][d*4+1] = f2tf32(v[d].y * qi);
            sQ[n][d*4+2] = f2tf32(v[d].z * qi);
            sQ[n][d*4+3] = f2tf32(v[d].w * qi);
        }
    }
    __syncthreads();

    uint32_t qf[4][2][4];
    #pragma unroll
    for (int kk = 0; kk < 4; kk++)
        #pragma unroll
        for (int mt = 0; mt < 2; mt++) {
            int r = wm + mt * 16;
            qf[kk][mt][0] = __float_as_uint(sQ[r + gid    ][kk*8 + tig    ]);
            qf[kk][mt][1] = __float_as_uint(sQ[r + gid + 8][kk*8 + tig    ]);
            qf[kk][mt][2] = __float_as_uint(sQ[r + gid    ][kk*8 + tig + 4]);
            qf[kk][mt][3] = __float_as_uint(sQ[r + gid + 8][kk*8 + tig + 4]);
        }

    float accO[2][4][4];
    #pragma unroll
    for (int mt = 0; mt < 2; mt++)
        #pragma unroll
        for (int nt = 0; nt < 4; nt++)
            #pragma unroll
            for (int r = 0; r < 4; r++) accO[mt][nt][r] = 0.f;
    float den[2][2] = {{0.f,0.f},{0.f,0.f}};

    for (int c = 0; c < 4; c++) {
        int st = c & 1;
        if (c < 3) prefetch(st ^ 1, c + 1);
        if (c < 3) cp_wait<1>(); else cp_wait<0>();
        __syncthreads();   // stage[st] ready; prior chunk's sK/sV fully consumed

        // normalize + round from staged smem into sK / sV
        if (tid < 64) {
            const float4* src = (const float4*)(stage + ((st * 2 + 0) * 64 + tid) * APAD);
            float4 v[8]; float ss = 0.f;
            #pragma unroll
            for (int d = 0; d < 8; d++) {
                v[d] = src[d];
                ss += v[d].x*v[d].x + v[d].y*v[d].y + v[d].z*v[d].z + v[d].w*v[d].w;
            }
            float ki = 1.f / fmaxf(sqrtf(ss), 1e-12f);
            #pragma unroll
            for (int d = 0; d < 8; d++) {
                sK[tid][d*4+0] = f2tf32(v[d].x * ki);
                sK[tid][d*4+1] = f2tf32(v[d].y * ki);
                sK[tid][d*4+2] = f2tf32(v[d].z * ki);
                sK[tid][d*4+3] = f2tf32(v[d].w * ki);
            }
        } else if (tid < 128) {
            int mm = tid - 64;
            const float4* src = (const float4*)(stage + ((st * 2 + 1) * 64 + mm) * APAD);
            #pragma unroll
            for (int d = 0; d < 8; d++) {
                float4 v = src[d];
                sV[mm][d*4+0] = f2tf32(v.x);
                sV[mm][d*4+1] = f2tf32(v.y);
                sV[mm][d*4+2] = f2tf32(v.z);
                sV[mm][d*4+3] = f2tf32(v.w);
            }
        }
        __syncthreads();

        float accS[2][8][4];
        #pragma unroll
        for (int mt = 0; mt < 2; mt++)
            #pragma unroll
            for (int nt = 0; nt < 8; nt++)
                #pragma unroll
                for (int r = 0; r < 4; r++) accS[mt][nt][r] = 0.f;

        #pragma unroll
        for (int kk = 0; kk < 4; kk++) {
            uint32_t bf[8][2];
            #pragma unroll
            for (int nt = 0; nt < 8; nt++) {
                int key = nt * 8 + gid;
                bf[nt][0] = __float_as_uint(sK[key][kk*8 + tig    ]);
                bf[nt][1] = __float_as_uint(sK[key][kk*8 + tig + 4]);
            }
            #pragma unroll
            for (int mt = 0; mt < 2; mt++)
                #pragma unroll
                for (int nt = 0; nt < 8; nt++)
                    mma_tf32(accS[mt][nt][0], accS[mt][nt][1], accS[mt][nt][2], accS[mt][nt][3],
                             qf[kk][mt][0], qf[kk][mt][1], qf[kk][mt][2], qf[kk][mt][3],
                             bf[nt][0], bf[nt][1]);
        }

        #pragma unroll
        for (int mt = 0; mt < 2; mt++) {
            int r_lo = wm + mt * 16 + gid, r_hi = r_lo + 8;
            const float* b_lo = g_biasw + ((size_t)h * NTOK_W + r_lo) * NTOK_W + c * 64 + tig * 2;
            const float* b_hi = g_biasw + ((size_t)h * NTOK_W + r_hi) * NTOK_W + c * 64 + tig * 2;
            #pragma unroll
            for (int nt = 0; nt < 8; nt++) {
                float2 bl = *(const float2*)(b_lo + nt * 8);
                float2 bh = *(const float2*)(b_hi + nt * 8);
                float p0 = __expf(accS[mt][nt][0] + bl.x - shift);
                float p1 = __expf(accS[mt][nt][1] + bl.y - shift);
                float p2 = __expf(accS[mt][nt][2] + bh.x - shift);
                float p3 = __expf(accS[mt][nt][3] + bh.y - shift);
                den[mt][0] += p0 + p1;
                den[mt][1] += p2 + p3;
                int col = nt * 8 + tig * 2;
                *(float2*)&sP[r_lo][col] = make_float2(f2tf32(p0), f2tf32(p1));
                *(float2*)&sP[r_hi][col] = make_float2(f2tf32(p2), f2tf32(p3));
            }
        }
        __syncwarp();

        #pragma unroll
        for (int kk2 = 0; kk2 < 8; kk2++) {
            uint32_t af[2][4];
            #pragma unroll
            for (int mt = 0; mt < 2; mt++) {
                int r = wm + mt * 16;
                af[mt][0] = __float_as_uint(sP[r + gid    ][kk2*8 + tig    ]);
                af[mt][1] = __float_as_uint(sP[r + gid + 8][kk2*8 + tig    ]);
                af[mt][2] = __float_as_uint(sP[r + gid    ][kk2*8 + tig + 4]);
                af[mt][3] = __float_as_uint(sP[r + gid + 8][kk2*8 + tig + 4]);
            }
            uint32_t vf[4][2];
            #pragma unroll
            for (int nt = 0; nt < 4; nt++) {
                int d = nt * 8 + gid;
                vf[nt][0] = __float_as_uint(sV[kk2*8 + tig    ][d]);
                vf[nt][1] = __float_as_uint(sV[kk2*8 + tig + 4][d]);
            }
            #pragma unroll
            for (int mt = 0; mt < 2; mt++)
                #pragma unroll
                for (int nt = 0; nt < 4; nt++)
                    mma_tf32(accO[mt][nt][0], accO[mt][nt][1], accO[mt][nt][2], accO[mt][nt][3],
                             af[mt][0], af[mt][1], af[mt][2], af[mt][3],
                             vf[nt][0], vf[nt][1]);
        }
    }

    #pragma unroll
    for (int mt = 0; mt < 2; mt++)
        #pragma unroll
        for (int j = 0; j < 2; j++) {
            den[mt][j] += __shfl_xor_sync(0xffffffffu, den[mt][j], 1);
            den[mt][j] += __shfl_xor_sync(0xffffffffu, den[mt][j], 2);
        }

    #pragma unroll
    for (int mt = 0; mt < 2; mt++) {
        int r_lo = wm + mt * 16 + gid, r_hi = r_lo + 8;
        float ri_lo = 1.f / den[mt][0], ri_hi = 1.f / den[mt][1];
        int qr_lo = (wh * WS + (r_lo >> 4)) * WIMG + ww * WS + (r_lo & 15);
        int qr_hi = (wh * WS + (r_hi >> 4)) * WIMG + ww * WS + (r_hi & 15);
        #pragma unroll
        for (int nt = 0; nt < 4; nt++) {
            int col = nt * 8 + tig * 2;
            *(float2*)&g_merged[(size_t)qr_lo * CDIM + h * HD + col] =
                make_float2(f2tf32(accO[mt][nt][0] * ri_lo), f2tf32(accO[mt][nt][1] * ri_lo));
            *(float2*)&g_merged[(size_t)qr_hi * CDIM + h * HD + col] =
                make_float2(f2tf32(accO[mt][nt][2] * ri_hi), f2tf32(accO[mt][nt][3] * ri_hi));
        }
    }
}

// ---- a1: 64 anchor queries x 16 chunks of 64 stripe keys -> xm (R6 exact) ----
__global__ __launch_bounds__(128) void a1_attn_mma(const float* __restrict__ ls) {
    __shared__ float sQ[64][APAD];
    __shared__ float sK[64][APAD];
    __shared__ float sV[64][APAD];
    __shared__ float sP[64][PPAD];

    int h = blockIdx.x & 3, sidx = blockIdx.x >> 2;
    int sh = sidx >> 3, sw = sidx & 7;
    int tid = threadIdx.x, wid = tid >> 5, lane = tid & 31;
    int gid = lane >> 2, tig = lane & 3;
    int wm = wid * 16;
    float scale = __expf(fminf(ls[h], LOG100));
    float shift = scale + 16.f;

    if (tid < 64) {
        int ap = (sh * ASZ + (tid >> 3)) * AH + sw * ASZ + (tid & 7);
        const float4* src = (const float4*)(g_ancn + (size_t)ap * 128 + h * HD);
        #pragma unroll
        for (int d = 0; d < 8; d++) {
            float4 v = src[d];
            sQ[tid][d*4+0] = f2tf32(v.x * scale);
            sQ[tid][d*4+1] = f2tf32(v.y * scale);
            sQ[tid][d*4+2] = f2tf32(v.z * scale);
            sQ[tid][d*4+3] = f2tf32(v.w * scale);
        }
    }
    __syncthreads();

    uint32_t qf[4][4];
    #pragma unroll
    for (int kk = 0; kk < 4; kk++) {
        qf[kk][0] = __float_as_uint(sQ[wm + gid    ][kk*8 + tig    ]);
        qf[kk][1] = __float_as_uint(sQ[wm + gid + 8][kk*8 + tig    ]);
        qf[kk][2] = __float_as_uint(sQ[wm + gid    ][kk*8 + tig + 4]);
        qf[kk][3] = __float_as_uint(sQ[wm + gid + 8][kk*8 + tig + 4]);
    }

    float accO[4][4];
    #pragma unroll
    for (int nt = 0; nt < 4; nt++)
        #pragma unroll
        for (int r = 0; r < 4; r++) accO[nt][r] = 0.f;
    float den[2] = {0.f, 0.f};

    for (int c = 0; c < 16; c++) {
        __syncthreads();
        if (tid < 64) {
            int m = c * 64 + tid;
            int krow = (sh * SS + (m >> 5)) * WIMG + sw * SS + (m & 31);
            const float4* src = (const float4*)(g_qkv + (size_t)krow * QKVC + 512 + h * HD);
            float4 v[8]; float ss = 0.f;
            #pragma unroll
            for (int d = 0; d < 8; d++) {
                v[d] = src[d];
                ss += v[d].x*v[d].x + v[d].y*v[d].y + v[d].z*v[d].z + v[d].w*v[d].w;
            }
            float ki = 1.f / fmaxf(sqrtf(ss), 1e-12f);
            #pragma unroll
            for (int d = 0; d < 8; d++) {
                sK[tid][d*4+0] = f2tf32(v[d].x * ki);
                sK[tid][d*4+1] = f2tf32(v[d].y * ki);
                sK[tid][d*4+2] = f2tf32(v[d].z * ki);
                sK[tid][d*4+3] = f2tf32(v[d].w * ki);
            }
        } else {
            int mm = tid - 64;
            int m = c * 64 + mm;
            int krow = (sh * SS + (m >> 5)) * WIMG + sw * SS + (m & 31);
            const float4* src = (const float4*)(g_qkv + (size_t)krow * QKVC + 640 + h * HD);
            #pragma unroll
            for (int d = 0; d < 8; d++) {
                float4 v = src[d];
                sV[mm][d*4+0] = f2tf32(v.x);
                sV[mm][d*4+1] = f2tf32(v.y);
                sV[mm][d*4+2] = f2tf32(v.z);
                sV[mm][d*4+3] = f2tf32(v.w);
            }
        }
        __syncthreads();

        float accS[8][4];
        #pragma unroll
        for (int nt = 0; nt < 8; nt++)
            #pragma unroll
            for (int r = 0; r < 4; r++) accS[nt][r] = 0.f;

        #pragma unroll
        for (int kk = 0; kk < 4; kk++) {
            uint32_t bf[8][2];
            #pragma unroll
            for (int nt = 0; nt < 8; nt++) {
                int key = nt * 8 + gid;
                bf[nt][0] = __float_as_uint(sK[key][kk*8 + tig    ]);
                bf[nt][1] = __float_as_uint(sK[key][kk*8 + tig + 4]);
            }
            #pragma unroll
            for (int nt = 0; nt < 8; nt++)
                mma_tf32(accS[nt][0], accS[nt][1], accS[nt][2], accS[nt][3],
                         qf[kk][0], qf[kk][1], qf[kk][2], qf[kk][3],
                         bf[nt][0], bf[nt][1]);
        }

        {
            int r_lo = wm + gid, r_hi = r_lo + 8;
            const float* b_lo = g_biasa1 + ((size_t)h * NANC + r_lo) * NTOK_S + c * 64 + tig * 2;
            const float* b_hi = g_biasa1 + ((size_t)h * NANC + r_hi) * NTOK_S + c * 64 + tig * 2;
            #pragma unroll
            for (int nt = 0; nt < 8; nt++) {
                float2 bl = *(const float2*)(b_lo + nt * 8);
                float2 bh = *(const float2*)(b_hi + nt * 8);
                float p0 = __expf(accS[nt][0] + bl.x - shift);
                float p1 = __expf(accS[nt][1] + bl.y - shift);
                float p2 = __expf(accS[nt][2] + bh.x - shift);
                float p3 = __expf(accS[nt][3] + bh.y - shift);
                den[0] += p0 + p1;
                den[1] += p2 + p3;
                int col = nt * 8 + tig * 2;
                *(float2*)&sP[r_lo][col] = make_float2(f2tf32(p0), f2tf32(p1));
                *(float2*)&sP[r_hi][col] = make_float2(f2tf32(p2), f2tf32(p3));
            }
        }
        __syncwarp();

        #pragma unroll
        for (int kk2 = 0; kk2 < 8; kk2++) {
            uint32_t af[4];
            af[0] = __float_as_uint(sP[wm + gid    ][kk2*8 + tig    ]);
            af[1] = __float_as_uint(sP[wm + gid + 8][kk2*8 + tig    ]);
            af[2] = __float_as_uint(sP[wm + gid    ][kk2*8 + tig + 4]);
            af[3] = __float_as_uint(sP[wm + gid + 8][kk2*8 + tig + 4]);
            uint32_t vf[4][2];
            #pragma unroll
            for (int nt = 0; nt < 4; nt++) {
                int d = nt * 8 + gid;
                vf[nt][0] = __float_as_uint(sV[kk2*8 + tig    ][d]);
                vf[nt][1] = __float_as_uint(sV[kk2*8 + tig + 4][d]);
            }
            #pragma unroll
            for (int nt = 0; nt < 4; nt++)
                mma_tf32(accO[nt][0], accO[nt][1], accO[nt][2], accO[nt][3],
                         af[0], af[1], af[2], af[3], vf[nt][0], vf[nt][1]);
        }
    }

    #pragma unroll
    for (int j = 0; j < 2; j++) {
        den[j] += __shfl_xor_sync(0xffffffffu, den[j], 1);
        den[j] += __shfl_xor_sync(0xffffffffu, den[j], 2);
    }

    {
        int r_lo = wm + gid, r_hi = r_lo + 8;
        float ri_lo = 1.f / den[0], ri_hi = 1.f / den[1];
        float* o_lo = g_xm + (((size_t)sidx * NHEAD + h) * NANC + r_lo) * HD;
        float* o_hi = g_xm + (((size_t)sidx * NHEAD + h) * NANC + r_hi) * HD;
        #pragma unroll
        for (int nt = 0; nt < 4; nt++) {
            int col = nt * 8 + tig * 2;
            *(float2*)(o_lo + col) = make_float2(accO[nt][0] * ri_lo, accO[nt][1] * ri_lo);
            *(float2*)(o_hi + col) = make_float2(accO[nt][2] * ri_hi, accO[nt][3] * ri_hi);
        }
    }
}

// ---- a2: 256-query chunk x 64 anchors, V = xm (R6 exact) ----
__global__ __launch_bounds__(256) void a2_attn_mma(const float* __restrict__ ls) {
    extern __shared__ float sm[];
    float (*sQ)[APAD] = (float(*)[APAD])sm;
    float (*sK)[APAD] = (float(*)[APAD])(sm + 256 * APAD);
    float (*sV)[APAD] = (float(*)[APAD])(sm + 320 * APAD);
    float (*sP)[PPAD] = (float(*)[PPAD])(sm + 384 * APAD);

    int b = blockIdx.x;
    int qc = b & 3, h = (b >> 2) & 3, sidx = b >> 4;
    int sh = sidx >> 3, sw = sidx & 7;
    int tid = threadIdx.x, wid = tid >> 5, lane = tid & 31;
    int gid = lane >> 2, tig = lane & 3;
    int wm = wid * 32;
    float scale = __expf(fminf(ls[h], LOG100));
    float shift = scale + 16.f;

    {
        int n = qc * 256 + tid;
        int qrow = (sh * SS + (n >> 5)) * WIMG + sw * SS + (n & 31);
        const float4* src = (const float4*)(g_qkv + (size_t)qrow * QKVC + 384 + h * HD);
        float4 v[8]; float ss = 0.f;
        #pragma unroll
        for (int d = 0; d < 8; d++) {
            v[d] = src[d];
            ss += v[d].x*v[d].x + v[d].y*v[d].y + v[d].z*v[d].z + v[d].w*v[d].w;
        }
        float qi = scale / fmaxf(sqrtf(ss), 1e-12f);
        #pragma unroll
        for (int d = 0; d < 8; d++) {
            sQ[tid][d*4+0] = f2tf32(v[d].x * qi);
            sQ[tid][d*4+1] = f2tf32(v[d].y * qi);
            sQ[tid][d*4+2] = f2tf32(v[d].z * qi);
            sQ[tid][d*4+3] = f2tf32(v[d].w * qi);
        }
    }
    if (tid < 64) {
        int ap = (sh * ASZ + (tid >> 3)) * AH + sw * ASZ + (tid & 7);
        const float4* src = (const float4*)(g_ancn + (size_t)ap * 128 + h * HD);
        #pragma unroll
        for (int d = 0; d < 8; d++) {
            float4 v = src[d];
            sK[tid][d*4+0] = f2tf32(v.x); sK[tid][d*4+1] = f2tf32(v.y);
            sK[tid][d*4+2] = f2tf32(v.z); sK[tid][d*4+3] = f2tf32(v.w);
        }
    } else if (tid < 128) {
        int mm = tid - 64;
        const float4* src = (const float4*)(g_xm + (((size_t)sidx * NHEAD + h) * NANC + mm) * HD);
        #pragma unroll
        for (int d = 0; d < 8; d++) {
            float4 v = src[d];
            sV[mm][d*4+0] = f2tf32(v.x); sV[mm][d*4+1] = f2tf32(v.y);
            sV[mm][d*4+2] = f2tf32(v.z); sV[mm][d*4+3] = f2tf32(v.w);
        }
    }
    __syncthreads();

    uint32_t qf[4][2][4];
    #pragma unroll
    for (int kk = 0; kk < 4; kk++)
        #pragma unroll
        for (int mt = 0; mt < 2; mt++) {
            int r = wm + mt * 16;
            qf[kk][mt][0] = __float_as_uint(sQ[r + gid    ][kk*8 + tig    ]);
            qf[kk][mt][1] = __float_as_uint(sQ[r + gid + 8][kk*8 + tig    ]);
            qf[kk][mt][2] = __float_as_uint(sQ[r + gid    ][kk*8 + tig + 4]);
            qf[kk][mt][3] = __float_as_uint(sQ[r + gid + 8][kk*8 + tig + 4]);
        }

    float accS[2][8][4];
    #pragma unroll
    for (int mt = 0; mt < 2; mt++)
        #pragma unroll
        for (int nt = 0; nt < 8; nt++)
            #pragma unroll
            for (int r = 0; r < 4; r++) accS[mt][nt][r] = 0.f;

    #pragma unroll
    for (int kk = 0; kk < 4; kk++) {
        uint32_t bf[8][2];
        #pragma unroll
        for (int nt = 0; nt < 8; nt++) {
            int key = nt * 8 + gid;
            bf[nt][0] = __float_as_uint(sK[key][kk*8 + tig    ]);
            bf[nt][1] = __float_as_uint(sK[key][kk*8 + tig + 4]);
        }
        #pragma unroll
        for (int mt = 0; mt < 2; mt++)
            #pragma unroll
            for (int nt = 0; nt < 8; nt++)
                mma_tf32(accS[mt][nt][0], accS[mt][nt][1], accS[mt][nt][2], accS[mt][nt][3],
                         qf[kk][mt][0], qf[kk][mt][1], qf[kk][mt][2], qf[kk][mt][3],
                         bf[nt][0], bf[nt][1]);
    }

    float den[2][2] = {{0.f,0.f},{0.f,0.f}};
    #pragma unroll
    for (int mt = 0; mt < 2; mt++) {
        int r_lo = wm + mt * 16 + gid, r_hi = r_lo + 8;
        int n_lo = qc * 256 + r_lo, n_hi = qc * 256 + r_hi;
        const float* b_lo = g_biasw2a + ((size_t)h * NTOK_S + n_lo) * NANC + tig * 2;
        const float* b_hi = g_biasw2a + ((size_t)h * NTOK_S + n_hi) * NANC + tig * 2;
        #pragma unroll
        for (int nt = 0; nt < 8; nt++) {
            float2 bl = *(const float2*)(b_lo + nt * 8);
            float2 bh = *(const float2*)(b_hi + nt * 8);
            float p0 = __expf(accS[mt][nt][0] + bl.x - shift);
            float p1 = __expf(accS[mt][nt][1] + bl.y - shift);
            float p2 = __expf(accS[mt][nt][2] + bh.x - shift);
            float p3 = __expf(accS[mt][nt][3] + bh.y - shift);
            den[mt][0] += p0 + p1;
            den[mt][1] += p2 + p3;
            int col = nt * 8 + tig * 2;
            *(float2*)&sP[r_lo][col] = make_float2(f2tf32(p0), f2tf32(p1));
            *(float2*)&sP[r_hi][col] = make_float2(f2tf32(p2), f2tf32(p3));
        }
    }
    __syncwarp();

    float accO[2][4][4];
    #pragma unroll
    for (int mt = 0; mt < 2; mt++)
        #pragma unroll
        for (int nt = 0; nt < 4; nt++)
            #pragma unroll
            for (int r = 0; r < 4; r++) accO[mt][nt][r] = 0.f;

    #pragma unroll
    for (int kk2 = 0; kk2 < 8; kk2++) {
        uint32_t af[2][4];
        #pragma unroll
        for (int mt = 0; mt < 2; mt++) {
            int r = wm + mt * 16;
            af[mt][0] = __float_as_uint(sP[r + gid    ][kk2*8 + tig    ]);
            af[mt][1] = __float_as_uint(sP[r + gid + 8][kk2*8 + tig    ]);
            af[mt][2] = __float_as_uint(sP[r + gid    ][kk2*8 + tig + 4]);
            af[mt][3] = __float_as_uint(sP[r + gid + 8][kk2*8 + tig + 4]);
        }
        uint32_t vf[4][2];
        #pragma unroll
        for (int nt = 0; nt < 4; nt++) {
            int d = nt * 8 + gid;
            vf[nt][0] = __float_as_uint(sV[kk2*8 + tig    ][d]);
            vf[nt][1] = __float_as_uint(sV[kk2*8 + tig + 4][d]);
        }
        #pragma unroll
        for (int mt = 0; mt < 2; mt++)
            #pragma unroll
            for (int nt = 0; nt < 4; nt++)
                mma_tf32(accO[mt][nt][0], accO[mt][nt][1], accO[mt][nt][2], accO[mt][nt][3],
                         af[mt][0], af[mt][1], af[mt][2], af[mt][3],
                         vf[nt][0], vf[nt][1]);
    }

    #pragma unroll
    for (int mt = 0; mt < 2; mt++)
        #pragma unroll
        for (int j = 0; j < 2; j++) {
            den[mt][j] += __shfl_xor_sync(0xffffffffu, den[mt][j], 1);
            den[mt][j] += __shfl_xor_sync(0xffffffffu, den[mt][j], 2);
        }

    #pragma unroll
    for (int mt = 0; mt < 2; mt++) {
        int r_lo = wm + mt * 16 + gid, r_hi = r_lo + 8;
        int n_lo = qc * 256 + r_lo, n_hi = qc * 256 + r_hi;
        float ri_lo = 1.f / den[mt][0], ri_hi = 1.f / den[mt][1];
        int qr_lo = (sh * SS + (n_lo >> 5)) * WIMG + sw * SS + (n_lo & 31);
        int qr_hi = (sh * SS + (n_hi >> 5)) * WIMG + sw * SS + (n_hi & 31);
        #pragma unroll
        for (int nt = 0; nt < 4; nt++) {
            int col = nt * 8 + tig * 2;
            *(float2*)&g_merged[(size_t)qr_lo * CDIM + 128 + h * HD + col] =
                make_float2(f2tf32(accO[mt][nt][0] * ri_lo), f2tf32(accO[mt][nt][1] * ri_lo));
            *(float2*)&g_merged[(size_t)qr_hi * CDIM + 128 + h * HD + col] =
                make_float2(f2tf32(accO[mt][nt][2] * ri_hi), f2tf32(accO[mt][nt][3] * ri_hi));
        }
    }
}

// ---------------- launch (exact R6 DAG) ----------------
extern "C" void kernel_launch(void* const* d_in, const int* in_sizes, int n_in,
                              void* d_out, int out_size) {
    const float* x        = (const float*)d_in[0];
    const float* qkv_w    = (const float*)d_in[1];
    const float* qkv_b    = (const float*)d_in[2];
    const float* anchor_w = (const float*)d_in[3];
    const float* anchor_b = (const float*)d_in[4];
    const float* ls_w     = (const float*)d_in[5];
    const float* w1_w     = (const float*)d_in[6];
    const float* b1_w     = (const float*)d_in[7];
    const float* w2_w     = (const float*)d_in[8];
    const float* ls_s1    = (const float*)d_in[9];
    const float* w1_s1    = (const float*)d_in[10];
    const float* b1_s1    = (const float*)d_in[11];
    const float* w2_s1    = (const float*)d_in[12];
    const float* ls_s2    = (const float*)d_in[13];
    const float* w1_s2    = (const float*)d_in[14];
    const float* b1_s2    = (const float*)d_in[15];
    const float* w2_s2    = (const float*)d_in[16];
    const float* proj_w   = (const float*)d_in[17];
    const float* proj_b   = (const float*)d_in[18];
    const float* table_w  = (const float*)d_in[19];
    const float* table_s  = (const float*)d_in[20];
    const int*   index_w  = (const int*)d_in[21];
    const int*   index_a2w= (const int*)d_in[22];
    const int*   index_w2a= (const int*)d_in[23];
    float* out = (float*)d_out;

    float *p_qkv, *p_merged, *p_xr, *p_pooled, *p_anchor, *p_ancn;
    float *p_wqkv, *p_wanc, *p_wproj;
    float *p_btw, *p_bts1, *p_bts2, *p_biasw, *p_biasa1, *p_biasw2a;
    cudaGetSymbolAddress((void**)&p_qkv, g_qkv);
    cudaGetSymbolAddress((void**)&p_merged, g_merged);
    cudaGetSymbolAddress((void**)&p_xr, g_xr);
    cudaGetSymbolAddress((void**)&p_pooled, g_pooled);
    cudaGetSymbolAddress((void**)&p_anchor, g_anchor);
    cudaGetSymbolAddress((void**)&p_ancn, g_ancn);
    cudaGetSymbolAddress((void**)&p_wqkv, g_wqkv);
    cudaGetSymbolAddress((void**)&p_wanc, g_wanc);
    cudaGetSymbolAddress((void**)&p_wproj, g_wproj);
    cudaGetSymbolAddress((void**)&p_btw, g_btw);
    cudaGetSymbolAddress((void**)&p_bts1, g_bts1);
    cudaGetSymbolAddress((void**)&p_bts2, g_bts2);
    cudaGetSymbolAddress((void**)&p_biasw, g_biasw);
    cudaGetSymbolAddress((void**)&p_biasa1, g_biasa1);
    cudaGetSymbolAddress((void**)&p_biasw2a, g_biasw2a);

    static cudaStream_t s1 = 0, s2 = 0;
    static cudaEvent_t evW = 0, ev1 = 0, ev2 = 0, evQ = 0, ev3 = 0;
    static bool init_done = false;
    if (!init_done) {
        cudaFuncSetAttribute(gemm_tf32, cudaFuncAttributeMaxDynamicSharedMemorySize, GEMM_SMEM_BYTES);
        cudaFuncSetAttribute(win_attn_mma, cudaFuncAttributeMaxDynamicSharedMemorySize, WIN_SMEM_BYTES);
        cudaFuncSetAttribute(a2_attn_mma, cudaFuncAttributeMaxDynamicSharedMemorySize, ATT_SMEM_BYTES);
        cudaStreamCreateWithFlags(&s1, cudaStreamNonBlocking);
        cudaStreamCreateWithFlags(&s2, cudaStreamNonBlocking);
        cudaEventCreateWithFlags(&evW, cudaEventDisableTiming);
        cudaEventCreateWithFlags(&ev1, cudaEventDisableTiming);
        cudaEventCreateWithFlags(&ev2, cudaEventDisableTiming);
        cudaEventCreateWithFlags(&evQ, cudaEventDisableTiming);
        cudaEventCreateWithFlags(&ev3, cudaEventDisableTiming);
        init_done = true;
    }

    // ---- phase 1: weight rounding on main stream, fork side streams ----
    round_weights<<<((CDIM*QKVC + CDIM*128 + CDIM*CDIM)/4 + 255) / 256, 256>>>(qkv_w, anchor_w, proj_w);
    cudaEventRecord(evW, 0);

    // s1: CPB MLPs + bias gathers
    cudaStreamWaitEvent(s1, evW, 0);
    cpb_mlp3<<<dim3(12, 3), 128, 0, s1>>>(table_w, table_s,
                                          w1_w, b1_w, w2_w,
                                          w1_s1, b1_s1, w2_s1,
                                          w1_s2, b1_s2, w2_s2);
    gather_nat<<<(NHEAD * NTOK_W * NTOK_W + 255) / 256, 256, 0, s1>>>(p_btw, index_w, p_biasw, NTOK_W, NTOK_W);
    gather_nat<<<(NHEAD * NANC * NTOK_S + 255) / 256, 256, 0, s1>>>(p_bts1, index_a2w, p_biasa1, NANC, NTOK_S);
    gather_nat<<<(NHEAD * NTOK_S * NANC + 255) / 256, 256, 0, s1>>>(p_bts2, index_w2a, p_biasw2a, NTOK_S, NANC);
    cudaEventRecord(ev1, s1);

    // s2: anchor path
    cudaStreamWaitEvent(s2, evW, 0);
    avgpool4<<<4096, 256, 0, s2>>>(x, p_pooled);
    gemm_tf32<<<dim3(1, 4096 / 128), 256, GEMM_SMEM_BYTES, s2>>>(p_pooled, p_wanc, anchor_b, p_anchor, 4096, 128, CDIM);
    norm_anchor<<<(4096 * NHEAD + 255) / 256, 256, 0, s2>>>(p_anchor, p_ancn);
    cudaEventRecord(ev2, s2);

    // main: x rounding + qkv GEMM
    round_tf32_vec<<<(LTOK * CDIM / 4 + 255) / 256, 256>>>(x, p_xr, LTOK * CDIM / 4);
    gemm_tf32<<<dim3(QKVC / 128, LTOK / 128), 256, GEMM_SMEM_BYTES>>>(
        p_xr, p_wqkv, qkv_b, p_qkv, LTOK, QKVC, CDIM);

    // join
    cudaStreamWaitEvent(0, ev1, 0);
    cudaStreamWaitEvent(0, ev2, 0);
    cudaEventRecord(evQ, 0);

    // ---- phase 2: attention; win on main, a1->a2 chain on s1 ----
    cudaStreamWaitEvent(s1, evQ, 0);
    a1_attn_mma<<<64 * NHEAD, 128, 0, s1>>>(ls_s1);
    a2_attn_mma<<<64 * NHEAD * 4, 256, ATT_SMEM_BYTES, s1>>>(ls_s2);
    cudaEventRecord(ev3, s1);

    win_attn_mma<<<256 * NHEAD, 256, WIN_SMEM_BYTES>>>(ls_w);

    cudaStreamWaitEvent(0, ev3, 0);

    // ---- phase 3: output projection ----
    gemm_tf32<<<dim3(CDIM / 128, LTOK / 128), 256, GEMM_SMEM_BYTES>>>(p_merged, p_wproj, proj_b, out, LTOK, CDIM, CDIM);
}

// round 16
// speedup vs baseline: 1.2379x; 1.0248x over previous
#include <cuda_runtime.h>
#include <cuda_bf16.h>
#include <math.h>
#include <stdint.h>

// ---------------- problem constants ----------------
#define HIMG 256
#define WIMG 256
#define CDIM 256
#define LTOK (HIMG*WIMG)          // 65536
#define QKVC 768
#define NHEAD 4
#define HD 32
#define WS 16
#define NTOK_W 256
#define SS 32
#define NTOK_S 1024
#define ASZ 8
#define NANC 64
#define AH 64
#define TW_N 961
#define TS_N 1521
#define LOG100 4.60517018598809f

// ---------------- scratch (__device__ globals: no allocs allowed) ----------------
__device__ float g_qkv[(size_t)LTOK * QKVC];
__device__ float g_merged[(size_t)LTOK * CDIM];     // [xw | xs] tf32-rounded
__device__ float g_xr[(size_t)LTOK * CDIM];         // x tf32-rounded
__device__ float g_pooled[4096 * CDIM];
__device__ float g_anchor[4096 * 128];
__device__ float g_ancn[4096 * 128];
__device__ float g_xm[64 * NHEAD * NANC * HD];
__device__ float g_wqkv[CDIM * QKVC];
__device__ float g_wanc[CDIM * 128];
__device__ float g_wproj[CDIM * CDIM];
__device__ float g_btw[TW_N * NHEAD];
__device__ float g_bts1[TS_N * NHEAD];
__device__ float g_bts2[TS_N * NHEAD];
__device__ float g_biasw[NHEAD * NTOK_W * NTOK_W];    // [h][n][m]
__device__ float g_biasa1[NHEAD * NANC * NTOK_S];     // [h][n2=64][m=1024]
__device__ float g_biasw2a[NHEAD * NTOK_S * NANC];    // [h][n=1024][m=64]

// ---------------- helpers ----------------
__device__ __forceinline__ uint32_t f2tf32u(float x) {
    uint32_t u;
    asm("cvt.rna.tf32.f32 %0, %1;" : "=r"(u) : "f"(x));
    return u;
}
__device__ __forceinline__ float f2tf32(float x) { return __uint_as_float(f2tf32u(x)); }

__device__ __forceinline__ void mma_tf32(float& c0, float& c1, float& c2, float& c3,
                                         uint32_t a0, uint32_t a1, uint32_t a2, uint32_t a3,
                                         uint32_t b0, uint32_t b1) {
    asm volatile(
        "mma.sync.aligned.m16n8k8.row.col.f32.tf32.tf32.f32 "
        "{%0,%1,%2,%3}, {%4,%5,%6,%7}, {%8,%9}, {%0,%1,%2,%3};"
        : "+f"(c0), "+f"(c1), "+f"(c2), "+f"(c3)
        : "r"(a0), "r"(a1), "r"(a2), "r"(a3), "r"(b0), "r"(b1));
}

__device__ __forceinline__ void cp16(void* smem_dst, const void* gsrc) {
    uint32_t s = (uint32_t)__cvta_generic_to_shared(smem_dst);
    asm volatile("cp.async.cg.shared.global [%0], [%1], 16;" :: "r"(s), "l"(gsrc));
}
__device__ __forceinline__ void cp_commit() { asm volatile("cp.async.commit_group;"); }
template<int N> __device__ __forceinline__ void cp_wait() {
    asm volatile("cp.async.wait_group %0;" :: "n"(N));
}

// ---------------- rounding kernels ----------------
__global__ void round_tf32_vec(const float* __restrict__ in, float* __restrict__ out, int n4) {
    int i = blockIdx.x * blockDim.x + threadIdx.x;
    if (i >= n4) return;
    float4 v = ((const float4*)in)[i];
    v.x = f2tf32(v.x); v.y = f2tf32(v.y); v.z = f2tf32(v.z); v.w = f2tf32(v.w);
    ((float4*)out)[i] = v;
}

__global__ void round_weights(const float* __restrict__ qkv_w,
                              const float* __restrict__ anchor_w,
                              const float* __restrict__ proj_w) {
    int i = blockIdx.x * blockDim.x + threadIdx.x;
    int n_qkv = CDIM * QKVC / 4, n_anc = CDIM * 128 / 4, n_proj = CDIM * CDIM / 4;
    const float4* src; float4* dst; int idx;
    if (i < n_qkv) { src = (const float4*)qkv_w; dst = (float4*)g_wqkv; idx = i; }
    else if (i < n_qkv + n_anc) { src = (const float4*)anchor_w; dst = (float4*)g_wanc; idx = i - n_qkv; }
    else if (i < n_qkv + n_anc + n_proj) { src = (const float4*)proj_w; dst = (float4*)g_wproj; idx = i - n_qkv - n_anc; }
    else return;
    float4 v = src[idx];
    v.x = f2tf32(v.x); v.y = f2tf32(v.y); v.z = f2tf32(v.z); v.w = f2tf32(v.w);
    dst[idx] = v;
}

// ---------------- tf32 tensor-core GEMM, cp.async 3-stage ----------------
#define GEMM_SMEM_BYTES (3*(128*36 + 32*136)*4)
__global__ __launch_bounds__(256) void gemm_tf32(const float* __restrict__ A,
                                                 const float* __restrict__ B,
                                                 const float* __restrict__ bias,
                                                 float* __restrict__ C,
                                                 int M, int N, int K) {
    extern __shared__ float smem[];
    float (*As)[128][36] = (float(*)[128][36])smem;
    float (*Bs)[32][136] = (float(*)[32][136])(smem + 3 * 128 * 36);

    int tid = threadIdx.x;
    int wid = tid >> 5;
    int lane = tid & 31;
    int gid = lane >> 2;
    int tig = lane & 3;
    int wm = (wid >> 2) * 64;
    int wn = (wid & 3) * 32;

    int row0 = blockIdx.y * 128;
    int col0 = blockIdx.x * 128;

    float acc[4][4][4];
    #pragma unroll
    for (int mt = 0; mt < 4; mt++)
        #pragma unroll
        for (int nt = 0; nt < 4; nt++)
            #pragma unroll
            for (int r = 0; r < 4; r++) acc[mt][nt][r] = 0.f;

    auto load_tile = [&](int st, int k0) {
        #pragma unroll
        for (int i = 0; i < 4; i++) {
            int f = tid + i * 256;
            int r = f >> 3, c4 = (f & 7) << 2;
            cp16(&As[st][r][c4], &A[(size_t)(row0 + r) * K + k0 + c4]);
        }
        #pragma unroll
        for (int i = 0; i < 4; i++) {
            int f = tid + i * 256;
            int r = f >> 5, c4 = (f & 31) << 2;
            cp16(&Bs[st][r][c4], &B[(size_t)(k0 + r) * N + col0 + c4]);
        }
        cp_commit();
    };

    int nk = K >> 5;
    load_tile(0, 0);
    if (nk > 1) load_tile(1, 32);
    for (int it = 0; it < nk; it++) {
        int st = it % 3;
        if (it + 2 < nk) { load_tile((it + 2) % 3, (it + 2) << 5); cp_wait<2>(); }
        else if (it + 1 < nk) cp_wait<1>();
        else cp_wait<0>();
        __syncthreads();

        #pragma unroll
        for (int kk = 0; kk < 32; kk += 8) {
            uint32_t af[4][4];
            #pragma unroll
            for (int mt = 0; mt < 4; mt++) {
                int rbase = wm + mt * 16;
                af[mt][0] = __float_as_uint(As[st][rbase + gid    ][kk + tig    ]);
                af[mt][1] = __float_as_uint(As[st][rbase + gid + 8][kk + tig    ]);
                af[mt][2] = __float_as_uint(As[st][rbase + gid    ][kk + tig + 4]);
                af[mt][3] = __float_as_uint(As[st][rbase + gid + 8][kk + tig + 4]);
            }
            uint32_t bf[4][2];
            #pragma unroll
            for (int nt = 0; nt < 4; nt++) {
                int cbase = wn + nt * 8 + gid;
                bf[nt][0] = __float_as_uint(Bs[st][kk + tig    ][cbase]);
                bf[nt][1] = __float_as_uint(Bs[st][kk + tig + 4][cbase]);
            }
            #pragma unroll
            for (int mt = 0; mt < 4; mt++)
                #pragma unroll
                for (int nt = 0; nt < 4; nt++)
                    mma_tf32(acc[mt][nt][0], acc[mt][nt][1], acc[mt][nt][2], acc[mt][nt][3],
                             af[mt][0], af[mt][1], af[mt][2], af[mt][3],
                             bf[nt][0], bf[nt][1]);
        }
        __syncthreads();
    }

    #pragma unroll
    for (int nt = 0; nt < 4; nt++) {
        int col = col0 + wn + nt * 8 + tig * 2;
        float b0 = bias[col], b1 = bias[col + 1];
        #pragma unroll
        for (int mt = 0; mt < 4; mt++) {
            int row = row0 + wm + mt * 16 + gid;
            float2 o0 = make_float2(acc[mt][nt][0] + b0, acc[mt][nt][1] + b1);
            float2 o1 = make_float2(acc[mt][nt][2] + b0, acc[mt][nt][3] + b1);
            *(float2*)&C[(size_t)row * N + col] = o0;
            *(float2*)&C[(size_t)(row + 8) * N + col] = o1;
        }
    }
}

// ---------------- CPB MLPs batched ----------------
__global__ void cpb_mlp3(const float* __restrict__ tw, const float* __restrict__ ts,
                         const float* __restrict__ w1a, const float* __restrict__ b1a,
                         const float* __restrict__ w2a,
                         const float* __restrict__ w1b, const float* __restrict__ b1b,
                         const float* __restrict__ w2b,
                         const float* __restrict__ w1c, const float* __restrict__ b1c,
                         const float* __restrict__ w2c) {
    int set = blockIdx.y;
    const float* table = (set == 0) ? tw : ts;
    int T = (set == 0) ? TW_N : TS_N;
    const float* w1 = (set == 0) ? w1a : (set == 1) ? w1b : w1c;
    const float* b1 = (set == 0) ? b1a : (set == 1) ? b1b : b1c;
    const float* w2 = (set == 0) ? w2a : (set == 1) ? w2b : w2c;
    float* bt = (set == 0) ? g_btw : (set == 1) ? g_bts1 : g_bts2;

    __shared__ float s_w1[1024];
    __shared__ float s_b1[512];
    __shared__ float s_w2[2048];
    for (int i = threadIdx.x; i < 1024; i += blockDim.x) s_w1[i] = w1[i];
    for (int i = threadIdx.x; i < 512;  i += blockDim.x) s_b1[i] = b1[i];
    for (int i = threadIdx.x; i < 2048; i += blockDim.x) s_w2[i] = w2[i];
    __syncthreads();
    int t = blockIdx.x * blockDim.x + threadIdx.x;
    if (t >= T) return;
    float t0 = table[t * 2], t1 = table[t * 2 + 1];
    float a0 = 0.f, a1 = 0.f, a2 = 0.f, a3 = 0.f;
    for (int j = 0; j < 512; j++) {
        float hsum = fmaf(t0, s_w1[j], fmaf(t1, s_w1[512 + j], s_b1[j]));
        float hr = fmaxf(hsum, 0.f);
        a0 = fmaf(hr, s_w2[j * 4 + 0], a0);
        a1 = fmaf(hr, s_w2[j * 4 + 1], a1);
        a2 = fmaf(hr, s_w2[j * 4 + 2], a2);
        a3 = fmaf(hr, s_w2[j * 4 + 3], a3);
    }
    bt[t * 4 + 0] = a0; bt[t * 4 + 1] = a1; bt[t * 4 + 2] = a2; bt[t * 4 + 3] = a3;
}

// ---------------- natural-layout gather [h][n][m] ----------------
__global__ void gather_nat(const float* __restrict__ bt, const int* __restrict__ index,
                           float* __restrict__ out, int Nq, int Nk) {
    int i = blockIdx.x * blockDim.x + threadIdx.x;
    int total = NHEAD * Nq * Nk;
    if (i >= total) return;
    int m = i % Nk;
    int n = (i / Nk) % Nq;
    int h = i / (Nk * Nq);
    int id = index[n * Nk + m];
    float b = bt[id * 4 + h];
    out[i] = 16.f / (1.f + __expf(-b));   // out[h][n][m]
}

// ---------------- avg pool 4x4 (tf32-rounded output) ----------------
__global__ void avgpool4(const float* __restrict__ x, float* __restrict__ pooled) {
    int p = blockIdx.x;
    int ch = threadIdx.x;
    int ph = p >> 6, pw = p & 63;
    float s = 0.f;
    #pragma unroll
    for (int i = 0; i < 4; i++)
        #pragma unroll
        for (int j = 0; j < 4; j++)
            s += x[((size_t)((ph * 4 + i) * WIMG + pw * 4 + j)) * CDIM + ch];
    pooled[(size_t)p * CDIM + ch] = f2tf32(s * 0.0625f);
}

// ---------------- anchor l2 normalize ----------------
__global__ void norm_anchor(const float* __restrict__ a, float* __restrict__ an) {
    int i = blockIdx.x * blockDim.x + threadIdx.x;
    if (i >= 4096 * NHEAD) return;
    int p = i >> 2, h = i & 3;
    const float4* src = (const float4*)(a + (size_t)p * 128 + h * HD);
    float4 v[8];
    float ss = 0.f;
    #pragma unroll
    for (int d = 0; d < 8; d++) {
        v[d] = src[d];
        ss += v[d].x * v[d].x + v[d].y * v[d].y + v[d].z * v[d].z + v[d].w * v[d].w;
    }
    float inv = 1.f / fmaxf(sqrtf(ss), 1e-12f);
    float4* dst = (float4*)(an + (size_t)p * 128 + h * HD);
    #pragma unroll
    for (int d = 0; d < 8; d++) {
        v[d].x *= inv; v[d].y *= inv; v[d].z *= inv; v[d].w *= inv;
        dst[d] = v[d];
    }
}

// =========================================================================
// Tensor-core flash attention
// =========================================================================
#define APAD 36
#define PPAD 68
// a2 layout (R6): sQ 256*36 | sK 64*36 | sV 64*36 | sP 256*68
#define ATT_SMEM_FLOATS (256*APAD + 64*APAD + 64*APAD + 256*PPAD)
#define ATT_SMEM_BYTES (ATT_SMEM_FLOATS*4)
// win layout: above + cp.async stage [3 bufs][K|V][64][36]
#define WIN_SMEM_FLOATS (ATT_SMEM_FLOATS + 6*64*APAD)
#define WIN_SMEM_BYTES (WIN_SMEM_FLOATS*4)
// a1 layout: sQ 64*36 | sK 64*36 | sV 64*36 | sP 64*68 | stage [2][K|V][64][36]
#define A1_SMEM_FLOATS (64*APAD*3 + 64*PPAD + 4*64*APAD)
#define A1_SMEM_BYTES (A1_SMEM_FLOATS*4)

// ---- window attention: 256 queries x 4 chunks of 64 keys, 3-stage cp.async ----
__global__ __launch_bounds__(256) void win_attn_mma(const float* __restrict__ ls) {
    extern __shared__ float sm[];
    float (*sQ)[APAD] = (float(*)[APAD])sm;
    float (*sK)[APAD] = (float(*)[APAD])(sm + 256 * APAD);
    float (*sV)[APAD] = (float(*)[APAD])(sm + 320 * APAD);
    float (*sP)[PPAD] = (float(*)[PPAD])(sm + 384 * APAD);
    float* stage = sm + 384 * APAD + 256 * PPAD;       // [st(3)][half][64][36]

    int h = blockIdx.x & 3, win = blockIdx.x >> 2;
    int wh = win >> 4, ww = win & 15;
    int tid = threadIdx.x, wid = tid >> 5, lane = tid & 31;
    int gid = lane >> 2, tig = lane & 3;
    int wm = wid * 32;
    float scale = __expf(fminf(ls[h], LOG100));
    float shift = scale + 16.f;

    auto prefetch = [&](int st, int c) {
        #pragma unroll
        for (int i = 0; i < 4; i++) {
            int f = tid + i * 256;           // 0..1023: 512 K-f4 + 512 V-f4
            int half = f >> 9;
            int idx = f & 511;
            int row = idx >> 3, c4 = (idx & 7) * 4;
            int m = c * 64 + row;
            int krow = (wh * WS + (m >> 4)) * WIMG + ww * WS + (m & 15);
            const float* src = g_qkv + (size_t)krow * QKVC + 128 + half * 128 + h * HD + c4;
            float* dst = stage + ((st * 2 + half) * 64 + row) * APAD + c4;
            cp16(dst, src);
        }
        cp_commit();
    };
    prefetch(0, 0);
    prefetch(1, 1);

    {
        int n = tid;
        int qrow = (wh * WS + (n >> 4)) * WIMG + ww * WS + (n & 15);
        const float4* src = (const float4*)(g_qkv + (size_t)qrow * QKVC + h * HD);
        float4 v[8]; float ss = 0.f;
        #pragma unroll
        for (int d = 0; d < 8; d++) {
            v[d] = src[d];
            ss += v[d].x*v[d].x + v[d].y*v[d].y + v[d].z*v[d].z + v[d].w*v[d].w;
        }
        float qi = scale / fmaxf(sqrtf(ss), 1e-12f);
        #pragma unroll
        for (int d = 0; d < 8; d++) {
            sQ[n][d*4+0] = f2tf32(v[d].x * qi);
            sQ[n][d*4+1] = f2tf32(v[d].y * qi);
            sQ[n][d*4+2] = f2tf32(v[d].z * qi);
            sQ[n][d*4+3] = f2tf32(v[d].w * qi);
        }
    }
    __syncthreads();

    uint32_t qf[4][2][4];
    #pragma unroll
    for (int kk = 0; kk < 4; kk++)
        #pragma unroll
        for (int mt = 0; mt < 2; mt++) {
            int r = wm + mt * 16;
            qf[kk][mt][0] = __float_as_uint(sQ[r + gid    ][kk*8 + tig    ]);
            qf[kk][mt][1] = __float_as_uint(sQ[r + gid + 8][kk*8 + tig    ]);
            qf[kk][mt][2] = __float_as_uint(sQ[r + gid    ][kk*8 + tig + 4]);
            qf[kk][mt][3] = __float_as_uint(sQ[r + gid + 8][kk*8 + tig + 4]);
        }

    float accO[2][4][4];
    #pragma unroll
    for (int mt = 0; mt < 2; mt++)
        #pragma unroll
        for (int nt = 0; nt < 4; nt++)
            #pragma unroll
            for (int r = 0; r < 4; r++) accO[mt][nt][r] = 0.f;
    float den[2][2] = {{0.f,0.f},{0.f,0.f}};

    for (int c = 0; c < 4; c++) {
        int st = c % 3;
        if (c + 2 < 4) { prefetch((c + 2) % 3, c + 2); cp_wait<2>(); }
        else if (c + 1 < 4) cp_wait<1>();
        else cp_wait<0>();
        __syncthreads();   // stage[st] ready; prior chunk's sK/sV fully consumed

        // normalize + round from staged smem into sK / sV
        if (tid < 64) {
            const float4* src = (const float4*)(stage + ((st * 2 + 0) * 64 + tid) * APAD);
            float4 v[8]; float ss = 0.f;
            #pragma unroll
            for (int d = 0; d < 8; d++) {
                v[d] = src[d];
                ss += v[d].x*v[d].x + v[d].y*v[d].y + v[d].z*v[d].z + v[d].w*v[d].w;
            }
            float ki = 1.f / fmaxf(sqrtf(ss), 1e-12f);
            #pragma unroll
            for (int d = 0; d < 8; d++) {
                sK[tid][d*4+0] = f2tf32(v[d].x * ki);
                sK[tid][d*4+1] = f2tf32(v[d].y * ki);
                sK[tid][d*4+2] = f2tf32(v[d].z * ki);
                sK[tid][d*4+3] = f2tf32(v[d].w * ki);
            }
        } else if (tid < 128) {
            int mm = tid - 64;
            const float4* src = (const float4*)(stage + ((st * 2 + 1) * 64 + mm) * APAD);
            #pragma unroll
            for (int d = 0; d < 8; d++) {
                float4 v = src[d];
                sV[mm][d*4+0] = f2tf32(v.x);
                sV[mm][d*4+1] = f2tf32(v.y);
                sV[mm][d*4+2] = f2tf32(v.z);
                sV[mm][d*4+3] = f2tf32(v.w);
            }
        }
        __syncthreads();

        float accS[2][8][4];
        #pragma unroll
        for (int mt = 0; mt < 2; mt++)
            #pragma unroll
            for (int nt = 0; nt < 8; nt++)
                #pragma unroll
                for (int r = 0; r < 4; r++) accS[mt][nt][r] = 0.f;

        #pragma unroll
        for (int kk = 0; kk < 4; kk++) {
            uint32_t bf[8][2];
            #pragma unroll
            for (int nt = 0; nt < 8; nt++) {
                int key = nt * 8 + gid;
                bf[nt][0] = __float_as_uint(sK[key][kk*8 + tig    ]);
                bf[nt][1] = __float_as_uint(sK[key][kk*8 + tig + 4]);
            }
            #pragma unroll
            for (int mt = 0; mt < 2; mt++)
                #pragma unroll
                for (int nt = 0; nt < 8; nt++)
                    mma_tf32(accS[mt][nt][0], accS[mt][nt][1], accS[mt][nt][2], accS[mt][nt][3],
                             qf[kk][mt][0], qf[kk][mt][1], qf[kk][mt][2], qf[kk][mt][3],
                             bf[nt][0], bf[nt][1]);
        }

        #pragma unroll
        for (int mt = 0; mt < 2; mt++) {
            int r_lo = wm + mt * 16 + gid, r_hi = r_lo + 8;
            const float* b_lo = g_biasw + ((size_t)h * NTOK_W + r_lo) * NTOK_W + c * 64 + tig * 2;
            const float* b_hi = g_biasw + ((size_t)h * NTOK_W + r_hi) * NTOK_W + c * 64 + tig * 2;
            #pragma unroll
            for (int nt = 0; nt < 8; nt++) {
                float2 bl = *(const float2*)(b_lo + nt * 8);
                float2 bh = *(const float2*)(b_hi + nt * 8);
                float p0 = __expf(accS[mt][nt][0] + bl.x - shift);
                float p1 = __expf(accS[mt][nt][1] + bl.y - shift);
                float p2 = __expf(accS[mt][nt][2] + bh.x - shift);
                float p3 = __expf(accS[mt][nt][3] + bh.y - shift);
                den[mt][0] += p0 + p1;
                den[mt][1] += p2 + p3;
                int col = nt * 8 + tig * 2;
                *(float2*)&sP[r_lo][col] = make_float2(f2tf32(p0), f2tf32(p1));
                *(float2*)&sP[r_hi][col] = make_float2(f2tf32(p2), f2tf32(p3));
            }
        }
        __syncwarp();

        #pragma unroll
        for (int kk2 = 0; kk2 < 8; kk2++) {
            uint32_t af[2][4];
            #pragma unroll
            for (int mt = 0; mt < 2; mt++) {
                int r = wm + mt * 16;
                af[mt][0] = __float_as_uint(sP[r + gid    ][kk2*8 + tig    ]);
                af[mt][1] = __float_as_uint(sP[r + gid + 8][kk2*8 + tig    ]);
                af[mt][2] = __float_as_uint(sP[r + gid    ][kk2*8 + tig + 4]);
                af[mt][3] = __float_as_uint(sP[r + gid + 8][kk2*8 + tig + 4]);
            }
            uint32_t vf[4][2];
            #pragma unroll
            for (int nt = 0; nt < 4; nt++) {
                int d = nt * 8 + gid;
                vf[nt][0] = __float_as_uint(sV[kk2*8 + tig    ][d]);
                vf[nt][1] = __float_as_uint(sV[kk2*8 + tig + 4][d]);
            }
            #pragma unroll
            for (int mt = 0; mt < 2; mt++)
                #pragma unroll
                for (int nt = 0; nt < 4; nt++)
                    mma_tf32(accO[mt][nt][0], accO[mt][nt][1], accO[mt][nt][2], accO[mt][nt][3],
                             af[mt][0], af[mt][1], af[mt][2], af[mt][3],
                             vf[nt][0], vf[nt][1]);
        }
    }

    #pragma unroll
    for (int mt = 0; mt < 2; mt++)
        #pragma unroll
        for (int j = 0; j < 2; j++) {
            den[mt][j] += __shfl_xor_sync(0xffffffffu, den[mt][j], 1);
            den[mt][j] += __shfl_xor_sync(0xffffffffu, den[mt][j], 2);
        }

    #pragma unroll
    for (int mt = 0; mt < 2; mt++) {
        int r_lo = wm + mt * 16 + gid, r_hi = r_lo + 8;
        float ri_lo = 1.f / den[mt][0], ri_hi = 1.f / den[mt][1];
        int qr_lo = (wh * WS + (r_lo >> 4)) * WIMG + ww * WS + (r_lo & 15);
        int qr_hi = (wh * WS + (r_hi >> 4)) * WIMG + ww * WS + (r_hi & 15);
        #pragma unroll
        for (int nt = 0; nt < 4; nt++) {
            int col = nt * 8 + tig * 2;
            *(float2*)&g_merged[(size_t)qr_lo * CDIM + h * HD + col] =
                make_float2(f2tf32(accO[mt][nt][0] * ri_lo), f2tf32(accO[mt][nt][1] * ri_lo));
            *(float2*)&g_merged[(size_t)qr_hi * CDIM + h * HD + col] =
                make_float2(f2tf32(accO[mt][nt][2] * ri_hi), f2tf32(accO[mt][nt][3] * ri_hi));
        }
    }
}

// ---- a1: 64 anchor queries x 16 chunks of 64 stripe keys, 2-stage cp.async ----
__global__ __launch_bounds__(128) void a1_attn_mma(const float* __restrict__ ls) {
    extern __shared__ float sm[];
    float (*sQ)[APAD] = (float(*)[APAD])sm;
    float (*sK)[APAD] = (float(*)[APAD])(sm + 64 * APAD);
    float (*sV)[APAD] = (float(*)[APAD])(sm + 128 * APAD);
    float (*sP)[PPAD] = (float(*)[PPAD])(sm + 192 * APAD);
    float* stage = sm + 192 * APAD + 64 * PPAD;        // [st(2)][half][64][36]

    int h = blockIdx.x & 3, sidx = blockIdx.x >> 2;
    int sh = sidx >> 3, sw = sidx & 7;
    int tid = threadIdx.x, wid = tid >> 5, lane = tid & 31;
    int gid = lane >> 2, tig = lane & 3;
    int wm = wid * 16;
    float scale = __expf(fminf(ls[h], LOG100));
    float shift = scale + 16.f;

    auto prefetch = [&](int st, int c) {
        #pragma unroll
        for (int i = 0; i < 8; i++) {
            int f = tid + i * 128;           // 0..1023
            int half = f >> 9;
            int idx = f & 511;
            int row = idx >> 3, c4 = (idx & 7) * 4;
            int m = c * 64 + row;
            int krow = (sh * SS + (m >> 5)) * WIMG + sw * SS + (m & 31);
            const float* src = g_qkv + (size_t)krow * QKVC + 512 + half * 128 + h * HD + c4;
            float* dst = stage + ((st * 2 + half) * 64 + row) * APAD + c4;
            cp16(dst, src);
        }
        cp_commit();
    };
    prefetch(0, 0);

    if (tid < 64) {
        int ap = (sh * ASZ + (tid >> 3)) * AH + sw * ASZ + (tid & 7);
        const float4* src = (const float4*)(g_ancn + (size_t)ap * 128 + h * HD);
        #pragma unroll
        for (int d = 0; d < 8; d++) {
            float4 v = src[d];
            sQ[tid][d*4+0] = f2tf32(v.x * scale);
            sQ[tid][d*4+1] = f2tf32(v.y * scale);
            sQ[tid][d*4+2] = f2tf32(v.z * scale);
            sQ[tid][d*4+3] = f2tf32(v.w * scale);
        }
    }
    __syncthreads();

    uint32_t qf[4][4];
    #pragma unroll
    for (int kk = 0; kk < 4; kk++) {
        qf[kk][0] = __float_as_uint(sQ[wm + gid    ][kk*8 + tig    ]);
        qf[kk][1] = __float_as_uint(sQ[wm + gid + 8][kk*8 + tig    ]);
        qf[kk][2] = __float_as_uint(sQ[wm + gid    ][kk*8 + tig + 4]);
        qf[kk][3] = __float_as_uint(sQ[wm + gid + 8][kk*8 + tig + 4]);
    }

    float accO[4][4];
    #pragma unroll
    for (int nt = 0; nt < 4; nt++)
        #pragma unroll
        for (int r = 0; r < 4; r++) accO[nt][r] = 0.f;
    float den[2] = {0.f, 0.f};

    for (int c = 0; c < 16; c++) {
        int st = c & 1;
        if (c < 15) prefetch(st ^ 1, c + 1);
        if (c < 15) cp_wait<1>(); else cp_wait<0>();
        __syncthreads();

        if (tid < 64) {
            const float4* src = (const float4*)(stage + ((st * 2 + 0) * 64 + tid) * APAD);
            float4 v[8]; float ss = 0.f;
            #pragma unroll
            for (int d = 0; d < 8; d++) {
                v[d] = src[d];
                ss += v[d].x*v[d].x + v[d].y*v[d].y + v[d].z*v[d].z + v[d].w*v[d].w;
            }
            float ki = 1.f / fmaxf(sqrtf(ss), 1e-12f);
            #pragma unroll
            for (int d = 0; d < 8; d++) {
                sK[tid][d*4+0] = f2tf32(v[d].x * ki);
                sK[tid][d*4+1] = f2tf32(v[d].y * ki);
                sK[tid][d*4+2] = f2tf32(v[d].z * ki);
                sK[tid][d*4+3] = f2tf32(v[d].w * ki);
            }
        } else {
            int mm = tid - 64;
            const float4* src = (const float4*)(stage + ((st * 2 + 1) * 64 + mm) * APAD);
            #pragma unroll
            for (int d = 0; d < 8; d++) {
                float4 v = src[d];
                sV[mm][d*4+0] = f2tf32(v.x);
                sV[mm][d*4+1] = f2tf32(v.y);
                sV[mm][d*4+2] = f2tf32(v.z);
                sV[mm][d*4+3] = f2tf32(v.w);
            }
        }
        __syncthreads();

        float accS[8][4];
        #pragma unroll
        for (int nt = 0; nt < 8; nt++)
            #pragma unroll
            for (int r = 0; r < 4; r++) accS[nt][r] = 0.f;

        #pragma unroll
        for (int kk = 0; kk < 4; kk++) {
            uint32_t bf[8][2];
            #pragma unroll
            for (int nt = 0; nt < 8; nt++) {
                int key = nt * 8 + gid;
                bf[nt][0] = __float_as_uint(sK[key][kk*8 + tig    ]);
                bf[nt][1] = __float_as_uint(sK[key][kk*8 + tig + 4]);
            }
            #pragma unroll
            for (int nt = 0; nt < 8; nt++)
                mma_tf32(accS[nt][0], accS[nt][1], accS[nt][2], accS[nt][3],
                         qf[kk][0], qf[kk][1], qf[kk][2], qf[kk][3],
                         bf[nt][0], bf[nt][1]);
        }

        {
            int r_lo = wm + gid, r_hi = r_lo + 8;
            const float* b_lo = g_biasa1 + ((size_t)h * NANC + r_lo) * NTOK_S + c * 64 + tig * 2;
            const float* b_hi = g_biasa1 + ((size_t)h * NANC + r_hi) * NTOK_S + c * 64 + tig * 2;
            #pragma unroll
            for (int nt = 0; nt < 8; nt++) {
                float2 bl = *(const float2*)(b_lo + nt * 8);
                float2 bh = *(const float2*)(b_hi + nt * 8);
                float p0 = __expf(accS[nt][0] + bl.x - shift);
                float p1 = __expf(accS[nt][1] + bl.y - shift);
                float p2 = __expf(accS[nt][2] + bh.x - shift);
                float p3 = __expf(accS[nt][3] + bh.y - shift);
                den[0] += p0 + p1;
                den[1] += p2 + p3;
                int col = nt * 8 + tig * 2;
                *(float2*)&sP[r_lo][col] = make_float2(f2tf32(p0), f2tf32(p1));
                *(float2*)&sP[r_hi][col] = make_float2(f2tf32(p2), f2tf32(p3));
            }
        }
        __syncwarp();

        #pragma unroll
        for (int kk2 = 0; kk2 < 8; kk2++) {
            uint32_t af[4];
            af[0] = __float_as_uint(sP[wm + gid    ][kk2*8 + tig    ]);
            af[1] = __float_as_uint(sP[wm + gid + 8][kk2*8 + tig    ]);
            af[2] = __float_as_uint(sP[wm + gid    ][kk2*8 + tig + 4]);
            af[3] = __float_as_uint(sP[wm + gid + 8][kk2*8 + tig + 4]);
            uint32_t vf[4][2];
            #pragma unroll
            for (int nt = 0; nt < 4; nt++) {
                int d = nt * 8 + gid;
                vf[nt][0] = __float_as_uint(sV[kk2*8 + tig    ][d]);
                vf[nt][1] = __float_as_uint(sV[kk2*8 + tig + 4][d]);
            }
            #pragma unroll
            for (int nt = 0; nt < 4; nt++)
                mma_tf32(accO[nt][0], accO[nt][1], accO[nt][2], accO[nt][3],
                         af[0], af[1], af[2], af[3], vf[nt][0], vf[nt][1]);
        }
    }

    #pragma unroll
    for (int j = 0; j < 2; j++) {
        den[j] += __shfl_xor_sync(0xffffffffu, den[j], 1);
        den[j] += __shfl_xor_sync(0xffffffffu, den[j], 2);
    }

    {
        int r_lo = wm + gid, r_hi = r_lo + 8;
        float ri_lo = 1.f / den[0], ri_hi = 1.f / den[1];
        float* o_lo = g_xm + (((size_t)sidx * NHEAD + h) * NANC + r_lo) * HD;
        float* o_hi = g_xm + (((size_t)sidx * NHEAD + h) * NANC + r_hi) * HD;
        #pragma unroll
        for (int nt = 0; nt < 4; nt++) {
            int col = nt * 8 + tig * 2;
            *(float2*)(o_lo + col) = make_float2(accO[nt][0] * ri_lo, accO[nt][1] * ri_lo);
            *(float2*)(o_hi + col) = make_float2(accO[nt][2] * ri_hi, accO[nt][3] * ri_hi);
        }
    }
}

// ---- a2: 256-query chunk x 64 anchors, V = xm (R6 exact) ----
__global__ __launch_bounds__(256) void a2_attn_mma(const float* __restrict__ ls) {
    extern __shared__ float sm[];
    float (*sQ)[APAD] = (float(*)[APAD])sm;
    float (*sK)[APAD] = (float(*)[APAD])(sm + 256 * APAD);
    float (*sV)[APAD] = (float(*)[APAD])(sm + 320 * APAD);
    float (*sP)[PPAD] = (float(*)[PPAD])(sm + 384 * APAD);

    int b = blockIdx.x;
    int qc = b & 3, h = (b >> 2) & 3, sidx = b >> 4;
    int sh = sidx >> 3, sw = sidx & 7;
    int tid = threadIdx.x, wid = tid >> 5, lane = tid & 31;
    int gid = lane >> 2, tig = lane & 3;
    int wm = wid * 32;
    float scale = __expf(fminf(ls[h], LOG100));
    float shift = scale + 16.f;

    {
        int n = qc * 256 + tid;
        int qrow = (sh * SS + (n >> 5)) * WIMG + sw * SS + (n & 31);
        const float4* src = (const float4*)(g_qkv + (size_t)qrow * QKVC + 384 + h * HD);
        float4 v[8]; float ss = 0.f;
        #pragma unroll
        for (int d = 0; d < 8; d++) {
            v[d] = src[d];
            ss += v[d].x*v[d].x + v[d].y*v[d].y + v[d].z*v[d].z + v[d].w*v[d].w;
        }
        float qi = scale / fmaxf(sqrtf(ss), 1e-12f);
        #pragma unroll
        for (int d = 0; d < 8; d++) {
            sQ[tid][d*4+0] = f2tf32(v[d].x * qi);
            sQ[tid][d*4+1] = f2tf32(v[d].y * qi);
            sQ[tid][d*4+2] = f2tf32(v[d].z * qi);
            sQ[tid][d*4+3] = f2tf32(v[d].w * qi);
        }
    }
    if (tid < 64) {
        int ap = (sh * ASZ + (tid >> 3)) * AH + sw * ASZ + (tid & 7);
        const float4* src = (const float4*)(g_ancn + (size_t)ap * 128 + h * HD);
        #pragma unroll
        for (int d = 0; d < 8; d++) {
            float4 v = src[d];
            sK[tid][d*4+0] = f2tf32(v.x); sK[tid][d*4+1] = f2tf32(v.y);
            sK[tid][d*4+2] = f2tf32(v.z); sK[tid][d*4+3] = f2tf32(v.w);
        }
    } else if (tid < 128) {
        int mm = tid - 64;
        const float4* src = (const float4*)(g_xm + (((size_t)sidx * NHEAD + h) * NANC + mm) * HD);
        #pragma unroll
        for (int d = 0; d < 8; d++) {
            float4 v = src[d];
            sV[mm][d*4+0] = f2tf32(v.x); sV[mm][d*4+1] = f2tf32(v.y);
            sV[mm][d*4+2] = f2tf32(v.z); sV[mm][d*4+3] = f2tf32(v.w);
        }
    }
    __syncthreads();

    uint32_t qf[4][2][4];
    #pragma unroll
    for (int kk = 0; kk < 4; kk++)
        #pragma unroll
        for (int mt = 0; mt < 2; mt++) {
            int r = wm + mt * 16;
            qf[kk][mt][0] = __float_as_uint(sQ[r + gid    ][kk*8 + tig    ]);
            qf[kk][mt][1] = __float_as_uint(sQ[r + gid + 8][kk*8 + tig    ]);
            qf[kk][mt][2] = __float_as_uint(sQ[r + gid    ][kk*8 + tig + 4]);
            qf[kk][mt][3] = __float_as_uint(sQ[r + gid + 8][kk*8 + tig + 4]);
        }

    float accS[2][8][4];
    #pragma unroll
    for (int mt = 0; mt < 2; mt++)
        #pragma unroll
        for (int nt = 0; nt < 8; nt++)
            #pragma unroll
            for (int r = 0; r < 4; r++) accS[mt][nt][r] = 0.f;

    #pragma unroll
    for (int kk = 0; kk < 4; kk++) {
        uint32_t bf[8][2];
        #pragma unroll
        for (int nt = 0; nt < 8; nt++) {
            int key = nt * 8 + gid;
            bf[nt][0] = __float_as_uint(sK[key][kk*8 + tig    ]);
            bf[nt][1] = __float_as_uint(sK[key][kk*8 + tig + 4]);
        }
        #pragma unroll
        for (int mt = 0; mt < 2; mt++)
            #pragma unroll
            for (int nt = 0; nt < 8; nt++)
                mma_tf32(accS[mt][nt][0], accS[mt][nt][1], accS[mt][nt][2], accS[mt][nt][3],
                         qf[kk][mt][0], qf[kk][mt][1], qf[kk][mt][2], qf[kk][mt][3],
                         bf[nt][0], bf[nt][1]);
    }

    float den[2][2] = {{0.f,0.f},{0.f,0.f}};
    #pragma unroll
    for (int mt = 0; mt < 2; mt++) {
        int r_lo = wm + mt * 16 + gid, r_hi = r_lo + 8;
        int n_lo = qc * 256 + r_lo, n_hi = qc * 256 + r_hi;
        const float* b_lo = g_biasw2a + ((size_t)h * NTOK_S + n_lo) * NANC + tig * 2;
        const float* b_hi = g_biasw2a + ((size_t)h * NTOK_S + n_hi) * NANC + tig * 2;
        #pragma unroll
        for (int nt = 0; nt < 8; nt++) {
            float2 bl = *(const float2*)(b_lo + nt * 8);
            float2 bh = *(const float2*)(b_hi + nt * 8);
            float p0 = __expf(accS[mt][nt][0] + bl.x - shift);
            float p1 = __expf(accS[mt][nt][1] + bl.y - shift);
            float p2 = __expf(accS[mt][nt][2] + bh.x - shift);
            float p3 = __expf(accS[mt][nt][3] + bh.y - shift);
            den[mt][0] += p0 + p1;
            den[mt][1] += p2 + p3;
            int col = nt * 8 + tig * 2;
            *(float2*)&sP[r_lo][col] = make_float2(f2tf32(p0), f2tf32(p1));
            *(float2*)&sP[r_hi][col] = make_float2(f2tf32(p2), f2tf32(p3));
        }
    }
    __syncwarp();

    float accO[2][4][4];
    #pragma unroll
    for (int mt = 0; mt < 2; mt++)
        #pragma unroll
        for (int nt = 0; nt < 4; nt++)
            #pragma unroll
            for (int r = 0; r < 4; r++) accO[mt][nt][r] = 0.f;

    #pragma unroll
    for (int kk2 = 0; kk2 < 8; kk2++) {
        uint32_t af[2][4];
        #pragma unroll
        for (int mt = 0; mt < 2; mt++) {
            int r = wm + mt * 16;
            af[mt][0] = __float_as_uint(sP[r + gid    ][kk2*8 + tig    ]);
            af[mt][1] = __float_as_uint(sP[r + gid + 8][kk2*8 + tig    ]);
            af[mt][2] = __float_as_uint(sP[r + gid    ][kk2*8 + tig + 4]);
            af[mt][3] = __float_as_uint(sP[r + gid + 8][kk2*8 + tig + 4]);
        }
        uint32_t vf[4][2];
        #pragma unroll
        for (int nt = 0; nt < 4; nt++) {
            int d = nt * 8 + gid;
            vf[nt][0] = __float_as_uint(sV[kk2*8 + tig    ][d]);
            vf[nt][1] = __float_as_uint(sV[kk2*8 + tig + 4][d]);
        }
        #pragma unroll
        for (int mt = 0; mt < 2; mt++)
            #pragma unroll
            for (int nt = 0; nt < 4; nt++)
                mma_tf32(accO[mt][nt][0], accO[mt][nt][1], accO[mt][nt][2], accO[mt][nt][3],
                         af[mt][0], af[mt][1], af[mt][2], af[mt][3],
                         vf[nt][0], vf[nt][1]);
    }

    #pragma unroll
    for (int mt = 0; mt < 2; mt++)
        #pragma unroll
        for (int j = 0; j < 2; j++) {
            den[mt][j] += __shfl_xor_sync(0xffffffffu, den[mt][j], 1);
            den[mt][j] += __shfl_xor_sync(0xffffffffu, den[mt][j], 2);
        }

    #pragma unroll
    for (int mt = 0; mt < 2; mt++) {
        int r_lo = wm + mt * 16 + gid, r_hi = r_lo + 8;
        int n_lo = qc * 256 + r_lo, n_hi = qc * 256 + r_hi;
        float ri_lo = 1.f / den[mt][0], ri_hi = 1.f / den[mt][1];
        int qr_lo = (sh * SS + (n_lo >> 5)) * WIMG + sw * SS + (n_lo & 31);
        int qr_hi = (sh * SS + (n_hi >> 5)) * WIMG + sw * SS + (n_hi & 31);
        #pragma unroll
        for (int nt = 0; nt < 4; nt++) {
            int col = nt * 8 + tig * 2;
            *(float2*)&g_merged[(size_t)qr_lo * CDIM + 128 + h * HD + col] =
                make_float2(f2tf32(accO[mt][nt][0] * ri_lo), f2tf32(accO[mt][nt][1] * ri_lo));
            *(float2*)&g_merged[(size_t)qr_hi * CDIM + 128 + h * HD + col] =
                make_float2(f2tf32(accO[mt][nt][2] * ri_hi), f2tf32(accO[mt][nt][3] * ri_hi));
        }
    }
}

// ---------------- launch (exact R6 DAG) ----------------
extern "C" void kernel_launch(void* const* d_in, const int* in_sizes, int n_in,
                              void* d_out, int out_size) {
    const float* x        = (const float*)d_in[0];
    const float* qkv_w    = (const float*)d_in[1];
    const float* qkv_b    = (const float*)d_in[2];
    const float* anchor_w = (const float*)d_in[3];
    const float* anchor_b = (const float*)d_in[4];
    const float* ls_w     = (const float*)d_in[5];
    const float* w1_w     = (const float*)d_in[6];
    const float* b1_w     = (const float*)d_in[7];
    const float* w2_w     = (const float*)d_in[8];
    const float* ls_s1    = (const float*)d_in[9];
    const float* w1_s1    = (const float*)d_in[10];
    const float* b1_s1    = (const float*)d_in[11];
    const float* w2_s1    = (const float*)d_in[12];
    const float* ls_s2    = (const float*)d_in[13];
    const float* w1_s2    = (const float*)d_in[14];
    const float* b1_s2    = (const float*)d_in[15];
    const float* w2_s2    = (const float*)d_in[16];
    const float* proj_w   = (const float*)d_in[17];
    const float* proj_b   = (const float*)d_in[18];
    const float* table_w  = (const float*)d_in[19];
    const float* table_s  = (const float*)d_in[20];
    const int*   index_w  = (const int*)d_in[21];
    const int*   index_a2w= (const int*)d_in[22];
    const int*   index_w2a= (const int*)d_in[23];
    float* out = (float*)d_out;

    float *p_qkv, *p_merged, *p_xr, *p_pooled, *p_anchor, *p_ancn;
    float *p_wqkv, *p_wanc, *p_wproj;
    float *p_btw, *p_bts1, *p_bts2, *p_biasw, *p_biasa1, *p_biasw2a;
    cudaGetSymbolAddress((void**)&p_qkv, g_qkv);
    cudaGetSymbolAddress((void**)&p_merged, g_merged);
    cudaGetSymbolAddress((void**)&p_xr, g_xr);
    cudaGetSymbolAddress((void**)&p_pooled, g_pooled);
    cudaGetSymbolAddress((void**)&p_anchor, g_anchor);
    cudaGetSymbolAddress((void**)&p_ancn, g_ancn);
    cudaGetSymbolAddress((void**)&p_wqkv, g_wqkv);
    cudaGetSymbolAddress((void**)&p_wanc, g_wanc);
    cudaGetSymbolAddress((void**)&p_wproj, g_wproj);
    cudaGetSymbolAddress((void**)&p_btw, g_btw);
    cudaGetSymbolAddress((void**)&p_bts1, g_bts1);
    cudaGetSymbolAddress((void**)&p_bts2, g_bts2);
    cudaGetSymbolAddress((void**)&p_biasw, g_biasw);
    cudaGetSymbolAddress((void**)&p_biasa1, g_biasa1);
    cudaGetSymbolAddress((void**)&p_biasw2a, g_biasw2a);

    static cudaStream_t s1 = 0, s2 = 0;
    static cudaEvent_t evW = 0, ev1 = 0, ev2 = 0, evQ = 0, ev3 = 0;
    static bool init_done = false;
    if (!init_done) {
        cudaFuncSetAttribute(gemm_tf32, cudaFuncAttributeMaxDynamicSharedMemorySize, GEMM_SMEM_BYTES);
        cudaFuncSetAttribute(win_attn_mma, cudaFuncAttributeMaxDynamicSharedMemorySize, WIN_SMEM_BYTES);
        cudaFuncSetAttribute(a1_attn_mma, cudaFuncAttributeMaxDynamicSharedMemorySize, A1_SMEM_BYTES);
        cudaFuncSetAttribute(a2_attn_mma, cudaFuncAttributeMaxDynamicSharedMemorySize, ATT_SMEM_BYTES);
        cudaStreamCreateWithFlags(&s1, cudaStreamNonBlocking);
        cudaStreamCreateWithFlags(&s2, cudaStreamNonBlocking);
        cudaEventCreateWithFlags(&evW, cudaEventDisableTiming);
        cudaEventCreateWithFlags(&ev1, cudaEventDisableTiming);
        cudaEventCreateWithFlags(&ev2, cudaEventDisableTiming);
        cudaEventCreateWithFlags(&evQ, cudaEventDisableTiming);
        cudaEventCreateWithFlags(&ev3, cudaEventDisableTiming);
        init_done = true;
    }

    // ---- phase 1: weight rounding on main stream, fork side streams ----
    round_weights<<<((CDIM*QKVC + CDIM*128 + CDIM*CDIM)/4 + 255) / 256, 256>>>(qkv_w, anchor_w, proj_w);
    cudaEventRecord(evW, 0);

    // s1: CPB MLPs + bias gathers
    cudaStreamWaitEvent(s1, evW, 0);
    cpb_mlp3<<<dim3(12, 3), 128, 0, s1>>>(table_w, table_s,
                                          w1_w, b1_w, w2_w,
                                          w1_s1, b1_s1, w2_s1,
                                          w1_s2, b1_s2, w2_s2);
    gather_nat<<<(NHEAD * NTOK_W * NTOK_W + 255) / 256, 256, 0, s1>>>(p_btw, index_w, p_biasw, NTOK_W, NTOK_W);
    gather_nat<<<(NHEAD * NANC * NTOK_S + 255) / 256, 256, 0, s1>>>(p_bts1, index_a2w, p_biasa1, NANC, NTOK_S);
    gather_nat<<<(NHEAD * NTOK_S * NANC + 255) / 256, 256, 0, s1>>>(p_bts2, index_w2a, p_biasw2a, NTOK_S, NANC);
    cudaEventRecord(ev1, s1);

    // s2: anchor path
    cudaStreamWaitEvent(s2, evW, 0);
    avgpool4<<<4096, 256, 0, s2>>>(x, p_pooled);
    gemm_tf32<<<dim3(1, 4096 / 128), 256, GEMM_SMEM_BYTES, s2>>>(p_pooled, p_wanc, anchor_b, p_anchor, 4096, 128, CDIM);
    norm_anchor<<<(4096 * NHEAD + 255) / 256, 256, 0, s2>>>(p_anchor, p_ancn);
    cudaEventRecord(ev2, s2);

    // main: x rounding + qkv GEMM
    round_tf32_vec<<<(LTOK * CDIM / 4 + 255) / 256, 256>>>(x, p_xr, LTOK * CDIM / 4);
    gemm_tf32<<<dim3(QKVC / 128, LTOK / 128), 256, GEMM_SMEM_BYTES>>>(
        p_xr, p_wqkv, qkv_b, p_qkv, LTOK, QKVC, CDIM);

    // join
    cudaStreamWaitEvent(0, ev1, 0);
    cudaStreamWaitEvent(0, ev2, 0);
    cudaEventRecord(evQ, 0);

    // ---- phase 2: attention; win on main, a1->a2 chain on s1 ----
    cudaStreamWaitEvent(s1, evQ, 0);
    a1_attn_mma<<<64 * NHEAD, 128, A1_SMEM_BYTES, s1>>>(ls_s1);
    a2_attn_mma<<<64 * NHEAD * 4, 256, ATT_SMEM_BYTES, s1>>>(ls_s2);
    cudaEventRecord(ev3, s1);

    win_attn_mma<<<256 * NHEAD, 256, WIN_SMEM_BYTES>>>(ls_w);

    cudaStreamWaitEvent(0, ev3, 0);

    // ---- phase 3: output projection ----
    gemm_tf32<<<dim3(CDIM / 128, LTOK / 128), 256, GEMM_SMEM_BYTES>>>(p_merged, p_wproj, proj_b, out, LTOK, CDIM, CDIM);
}